// round 10
// baseline (speedup 1.0000x reference)
#include <cuda_runtime.h>
#include <cuda_fp16.h>
#include <math.h>
#include <stdint.h>

// ---------------- problem constants ----------------
#define T_TOK 16384
#define DIM   1024
#define HID   2048
#define NEXP  8
#define TOPK  2
#define NSLOT (T_TOK*TOPK)                 // 32768
#define PADT  (NSLOT + NEXP*128)           // 33792 padded rows
#define ROWB  (PADT/128)                   // 264 row-blocks

// ---------------- device scratch (allocation-free rule) ----------------
__device__ int   g_counts[NEXP];
__device__ int   g_cntpad[NEXP];
__device__ int   g_offsets[NEXP];
__device__ int   g_perm[PADT];
__device__ int   g_rowOf[NSLOT];
__device__ int   g_sel[NSLOT];
__device__ float g_gwt[NSLOT];

// fp16 weight hi/lo splits; fp16 activations (single)
__device__ __half g_w1h[(size_t)NEXP*HID*DIM];
__device__ __half g_w1l[(size_t)NEXP*HID*DIM];
__device__ __half g_w3h[(size_t)NEXP*HID*DIM];
__device__ __half g_w3l[(size_t)NEXP*HID*DIM];
__device__ __half g_w2h[(size_t)NEXP*DIM*HID];
__device__ __half g_w2l[(size_t)NEXP*DIM*HID];
__device__ __half g_x [(size_t)PADT*DIM];
__device__ __half g_h [(size_t)PADT*HID];
__device__ float  g_y [(size_t)PADT*DIM];

// ---------------- helpers (base-PTX only) ----------------
__device__ __forceinline__ uint32_t smem_u32(const void* p) {
    uint32_t a;
    asm("{ .reg .u64 t; cvta.to.shared.u64 t, %1; cvt.u32.u64 %0, t; }" : "=r"(a) : "l"(p));
    return a;
}
__device__ __forceinline__ void cp16(uint32_t dst, const void* src) {
    asm volatile("cp.async.cg.shared.global [%0], [%1], 16;" :: "r"(dst), "l"(src));
}
__device__ __forceinline__ void cp_commit() {
    asm volatile("cp.async.commit_group;");
}
__device__ __forceinline__ void cp_wait0() {
    asm volatile("cp.async.wait_group 0;" ::: "memory");
}
// m16n8k16 row.col fp16 -> f32 accum (base PTX)
__device__ __forceinline__ void mma_f16(float c[4], const uint32_t a[4],
                                        uint32_t b0, uint32_t b1) {
    asm volatile(
        "mma.sync.aligned.m16n8k16.row.col.f32.f16.f16.f32 "
        "{%0,%1,%2,%3}, {%4,%5,%6,%7}, {%8,%9}, {%0,%1,%2,%3};"
        : "+f"(c[0]), "+f"(c[1]), "+f"(c[2]), "+f"(c[3])
        : "r"(a[0]), "r"(a[1]), "r"(a[2]), "r"(a[3]), "r"(b0), "r"(b1));
}
__device__ __forceinline__ void ldm_x4(uint32_t* r, uint32_t a) {
    asm volatile("ldmatrix.sync.aligned.m8n8.x4.shared.b16 {%0,%1,%2,%3}, [%4];"
                 : "=r"(r[0]), "=r"(r[1]), "=r"(r[2]), "=r"(r[3]) : "r"(a));
}
__device__ __forceinline__ int expert_of(int row0) {
    int e = 0;
#pragma unroll
    for (int i = 1; i < NEXP; i++) if (row0 >= g_offsets[i]) e = i;
    return e;
}

// ---------------- launch 0: gating (1 warp / token) ------
__global__ void gating_kernel(const float* __restrict__ x, const float* __restrict__ gw) {
    int t = (blockIdx.x * blockDim.x + threadIdx.x) >> 5;
    int lane = threadIdx.x & 31;
    if (t >= T_TOK) return;
    const float* xr = x + (size_t)t * DIM;
    float xv[DIM / 32];
#pragma unroll
    for (int i = 0; i < DIM / 32; i++) xv[i] = xr[lane + 32 * i];
    float logits[NEXP];
#pragma unroll
    for (int e = 0; e < NEXP; e++) {
        const float* g = gw + e * DIM;
        float acc = 0.f;
#pragma unroll
        for (int i = 0; i < DIM / 32; i++) acc = fmaf(xv[i], g[lane + 32 * i], acc);
#pragma unroll
        for (int o = 16; o; o >>= 1) acc += __shfl_xor_sync(0xffffffffu, acc, o);
        logits[e] = acc;
    }
    if (lane == 0) {
        int e0 = 0; float l0 = logits[0];
#pragma unroll
        for (int e = 1; e < NEXP; e++) if (logits[e] > l0) { l0 = logits[e]; e0 = e; }
        int e1 = (e0 == 0) ? 1 : 0; float l1 = logits[e1];
#pragma unroll
        for (int e = 0; e < NEXP; e++) if (e != e0 && logits[e] > l1) { l1 = logits[e]; e1 = e; }
        float p1 = __expf(l1 - l0);
        float inv = 1.f / (1.f + p1);
        g_sel[t * 2 + 0] = e0; g_sel[t * 2 + 1] = e1;
        g_gwt[t * 2 + 0] = inv; g_gwt[t * 2 + 1] = p1 * inv;
    }
}

// ---------------- launch 1: count + scan + scatter (single block) -----------
__global__ __launch_bounds__(1024) void scatscan_kernel() {
    __shared__ int scnt[NEXP];
    __shared__ int scur[NEXP];
    int tid = threadIdx.x;
    if (tid < NEXP) scnt[tid] = 0;
    __syncthreads();
    for (int idx = tid; idx < NSLOT; idx += 1024)
        atomicAdd(&scnt[g_sel[idx]], 1);
    __syncthreads();
    if (tid == 0) {
        int o = 0;
        for (int e = 0; e < NEXP; e++) {
            int c = scnt[e];
            int cp = (c + 127) & ~127;
            g_counts[e] = c;
            g_offsets[e] = o;
            g_cntpad[e] = cp;
            scur[e] = o;
            o += cp;
        }
    }
    __syncthreads();
    for (int idx = tid; idx < NSLOT; idx += 1024) {
        int e = g_sel[idx];
        int pos = atomicAdd(&scur[e], 1);
        g_perm[pos] = idx >> 1;
        g_rowOf[idx] = pos;
    }
}

// ---------------- launch 2: prep = gather(x->fp16) + weight hi/lo fp16 ------
#define WQ ((size_t)NEXP*HID*DIM/4)
#define WBLK ((unsigned)((3*WQ + 255) / 256))
__global__ __launch_bounds__(256) void prep_kernel(const float* __restrict__ x,
                                                   const float* __restrict__ w1,
                                                   const float* __restrict__ w3,
                                                   const float* __restrict__ w2) {
    int b = blockIdx.x;
    if (b < PADT) {
        int row = b;
        int e = -1, r = 0;
#pragma unroll
        for (int i = 0; i < NEXP; i++) {
            int o = g_offsets[i], c = g_cntpad[i];
            if (row >= o && row < o + c) { e = i; r = row - o; }
        }
        if (e < 0) return;
        float4 v = make_float4(0.f, 0.f, 0.f, 0.f);
        if (r < g_counts[e]) {
            int tok = g_perm[row];
            v = *(const float4*)(x + (size_t)tok * DIM + threadIdx.x * 4);
        }
        size_t o = (size_t)row * DIM + threadIdx.x * 4;
        __half2 a0, a1;
        a0.x = __float2half_rn(v.x); a0.y = __float2half_rn(v.y);
        a1.x = __float2half_rn(v.z); a1.y = __float2half_rn(v.w);
        ((__half2*)(g_x + o))[0] = a0;
        ((__half2*)(g_x + o))[1] = a1;
    } else {
        size_t i = (size_t)(b - PADT) * 256 + threadIdx.x;
        if (i >= 3 * WQ) return;
        const float* src; __half *hi, *lo; size_t j;
        if (i < WQ)          { src = w1; hi = g_w1h; lo = g_w1l; j = i; }
        else if (i < 2 * WQ) { src = w3; hi = g_w3h; lo = g_w3l; j = i - WQ; }
        else                 { src = w2; hi = g_w2h; lo = g_w2l; j = i - 2 * WQ; }
        float4 v = ((const float4*)src)[j];
        __half2 h0, h1, l0, l1;
        h0.x = __float2half_rn(v.x); h0.y = __float2half_rn(v.y);
        h1.x = __float2half_rn(v.z); h1.y = __float2half_rn(v.w);
        l0.x = __float2half_rn(v.x - __half2float(h0.x));
        l0.y = __float2half_rn(v.y - __half2float(h0.y));
        l1.x = __float2half_rn(v.z - __half2float(h1.x));
        l1.y = __float2half_rn(v.w - __half2float(h1.y));
        ((__half2*)(hi + 4 * j))[0] = h0;
        ((__half2*)(hi + 4 * j))[1] = h1;
        ((__half2*)(lo + 4 * j))[0] = l0;
        ((__half2*)(lo + 4 * j))[1] = l1;
    }
}

// ---------------- shared memory layouts ----------------
#define SAW 80
// GEMM1: A [128x32], B1/B3 hi/lo [64x32] each
#define G1_A   0
#define G1_B1H 10240
#define G1_B1L 15360
#define G1_B3H 20480
#define G1_B3L 25600
#define G1_STAGE 30720
#define G1_SMEM (2*G1_STAGE)
// GEMM2: A [128x32], B hi/lo [64x32]
#define G2_A   0
#define G2_BH  10240
#define G2_BL  15360
#define G2_STAGE 20480
#define G2_SMEM (2*G2_STAGE)

// ---------------- GEMM1: hidden = silu(x@w1^T) * (x@w3^T), fp16 2-pass ------
__device__ __forceinline__ void g1_load(uint32_t st,
        const __half* A,
        const __half* B1h, const __half* B1l,
        const __half* B3h, const __half* B3l, int kt, int tid) {
#pragma unroll
    for (int i = 0; i < 2; i++) {
        int idx = tid + i * 256;
        int m = idx >> 2, c = idx & 3;
        cp16(st + G1_A + m * SAW + c * 16, A + (size_t)m * DIM + kt + c * 8);
    }
    {
        int n = tid >> 2, c = tid & 3;
        cp16(st + G1_B1H + n * SAW + c * 16, B1h + (size_t)n * DIM + kt + c * 8);
        cp16(st + G1_B1L + n * SAW + c * 16, B1l + (size_t)n * DIM + kt + c * 8);
        cp16(st + G1_B3H + n * SAW + c * 16, B3h + (size_t)n * DIM + kt + c * 8);
        cp16(st + G1_B3L + n * SAW + c * 16, B3l + (size_t)n * DIM + kt + c * 8);
    }
}

__global__ __launch_bounds__(256, 2) void gemm1_mma() {
    int row0 = blockIdx.y * 128;
    if (row0 >= g_offsets[NEXP - 1] + g_cntpad[NEXP - 1]) return;
    int e = expert_of(row0);
    int n0 = blockIdx.x * 64;

    extern __shared__ __align__(16) char smem[];
    uint32_t sb = smem_u32(smem);
    int tid = threadIdx.x, lane = tid & 31, warp = tid >> 5;
    int gr = lane >> 2, gc2 = (lane & 3) * 2;
    int wm = (warp & 3) * 32;
    int wn = (warp >> 2) * 32;

    const __half* A   = g_x + (size_t)row0 * DIM;
    const size_t wb = ((size_t)e * HID + n0) * DIM;
    const __half* B1h = g_w1h + wb;
    const __half* B1l = g_w1l + wb;
    const __half* B3h = g_w3h + wb;
    const __half* B3l = g_w3l + wb;

    float acc1[2][4][4], acc3[2][4][4];
#pragma unroll
    for (int i = 0; i < 2; i++)
#pragma unroll
        for (int j = 0; j < 4; j++)
#pragma unroll
            for (int q = 0; q < 4; q++) { acc1[i][j][q] = 0.f; acc3[i][j][q] = 0.f; }

    uint32_t aAddr = (lane & 15) * SAW + (lane >> 4) * 16;
    uint32_t bAddr = (((lane >> 4) & 1) * 8 + (lane & 7)) * SAW + ((lane >> 3) & 1) * 16;

    const int NK = DIM / 32;   // 32
    g1_load(sb, A, B1h, B1l, B3h, B3l, 0, tid);
    cp_commit();

#pragma unroll 1
    for (int kc = 0; kc < NK; kc++) {
        cp_wait0();
        __syncthreads();
        if (kc + 1 < NK) {
            g1_load(sb + ((kc + 1) & 1) * G1_STAGE, A, B1h, B1l, B3h, B3l,
                    (kc + 1) * 32, tid);
            cp_commit();
        }
        uint32_t stv = sb + (kc & 1) * G1_STAGE;
#pragma unroll
        for (int ks = 0; ks < 2; ks++) {
            uint32_t k0b = ks * 32;
            uint32_t a[2][4];
#pragma unroll
            for (int i = 0; i < 2; i++)
                ldm_x4(a[i], stv + G1_A + (wm + i * 16) * SAW + aAddr + k0b);
#pragma unroll
            for (int jp = 0; jp < 2; jp++) {
                uint32_t rb = (wn + jp * 16) * SAW + bAddr + k0b;
                int j0 = jp * 2, j1 = jp * 2 + 1;
                uint32_t bh[4], bl[4];
                ldm_x4(bh, stv + G1_B1H + rb);
                ldm_x4(bl, stv + G1_B1L + rb);
#pragma unroll
                for (int i = 0; i < 2; i++) {
                    mma_f16(acc1[i][j0], a[i], bh[0], bh[1]);
                    mma_f16(acc1[i][j1], a[i], bh[2], bh[3]);
                    mma_f16(acc1[i][j0], a[i], bl[0], bl[1]);
                    mma_f16(acc1[i][j1], a[i], bl[2], bl[3]);
                }
                ldm_x4(bh, stv + G1_B3H + rb);
                ldm_x4(bl, stv + G1_B3L + rb);
#pragma unroll
                for (int i = 0; i < 2; i++) {
                    mma_f16(acc3[i][j0], a[i], bh[0], bh[1]);
                    mma_f16(acc3[i][j1], a[i], bh[2], bh[3]);
                    mma_f16(acc3[i][j0], a[i], bl[0], bl[1]);
                    mma_f16(acc3[i][j1], a[i], bl[2], bl[3]);
                }
            }
        }
    }

    // epilogue: silu(h1)*h3 -> fp16 hidden
#pragma unroll
    for (int i = 0; i < 2; i++)
#pragma unroll
        for (int j = 0; j < 4; j++) {
            int m = wm + i * 16 + gr;
            int n = wn + j * 8 + gc2;
#pragma unroll
            for (int half = 0; half < 2; half++) {
                int mm = m + half * 8;
                float h1a = acc1[i][j][half * 2 + 0], h1b = acc1[i][j][half * 2 + 1];
                float h3a = acc3[i][j][half * 2 + 0], h3b = acc3[i][j][half * 2 + 1];
                float v0 = h3a * h1a / (1.f + __expf(-h1a));
                float v1 = h3b * h1b / (1.f + __expf(-h1b));
                __half2 hv;
                hv.x = __float2half_rn(v0);
                hv.y = __float2half_rn(v1);
                *(__half2*)(g_h + (size_t)(row0 + mm) * HID + n0 + n) = hv;
            }
        }
}

// ---------------- GEMM2: y = hidden @ w2^T, fp16 2-pass, tile 128x64 --------
__device__ __forceinline__ void g2_load(uint32_t st,
        const __half* A, const __half* Bh, const __half* Bl, int kt, int tid) {
#pragma unroll
    for (int i = 0; i < 2; i++) {
        int idx = tid + i * 256;
        int m = idx >> 2, c = idx & 3;
        cp16(st + G2_A + m * SAW + c * 16, A + (size_t)m * HID + kt + c * 8);
    }
    {
        int n = tid >> 2, c = tid & 3;
        cp16(st + G2_BH + n * SAW + c * 16, Bh + (size_t)n * HID + kt + c * 8);
        cp16(st + G2_BL + n * SAW + c * 16, Bl + (size_t)n * HID + kt + c * 8);
    }
}

__global__ __launch_bounds__(256, 2) void gemm2_mma() {
    int row0 = blockIdx.y * 128;
    if (row0 >= g_offsets[NEXP - 1] + g_cntpad[NEXP - 1]) return;
    int e = expert_of(row0);
    int n0 = blockIdx.x * 64;

    extern __shared__ __align__(16) char smem[];
    uint32_t sb = smem_u32(smem);
    int tid = threadIdx.x, lane = tid & 31, warp = tid >> 5;
    int gr = lane >> 2, gc2 = (lane & 3) * 2;
    int wm = (warp & 3) * 32;
    int wn = (warp >> 2) * 32;

    const __half* A  = g_h + (size_t)row0 * HID;
    const size_t wb = ((size_t)e * DIM + n0) * HID;
    const __half* Bh = g_w2h + wb;
    const __half* Bl = g_w2l + wb;

    float acc[2][4][4];
#pragma unroll
    for (int i = 0; i < 2; i++)
#pragma unroll
        for (int j = 0; j < 4; j++)
#pragma unroll
            for (int q = 0; q < 4; q++) acc[i][j][q] = 0.f;

    uint32_t aAddr = (lane & 15) * SAW + (lane >> 4) * 16;
    uint32_t bAddr = (((lane >> 4) & 1) * 8 + (lane & 7)) * SAW + ((lane >> 3) & 1) * 16;

    const int NK = HID / 32;   // 64
    g2_load(sb, A, Bh, Bl, 0, tid);
    cp_commit();

#pragma unroll 1
    for (int kc = 0; kc < NK; kc++) {
        cp_wait0();
        __syncthreads();
        if (kc + 1 < NK) {
            g2_load(sb + ((kc + 1) & 1) * G2_STAGE, A, Bh, Bl, (kc + 1) * 32, tid);
            cp_commit();
        }
        uint32_t stv = sb + (kc & 1) * G2_STAGE;
#pragma unroll
        for (int ks = 0; ks < 2; ks++) {
            uint32_t k0b = ks * 32;
            uint32_t a[2][4];
#pragma unroll
            for (int i = 0; i < 2; i++)
                ldm_x4(a[i], stv + G2_A + (wm + i * 16) * SAW + aAddr + k0b);
#pragma unroll
            for (int jp = 0; jp < 2; jp++) {
                uint32_t rb = (wn + jp * 16) * SAW + bAddr + k0b;
                int j0 = jp * 2, j1 = jp * 2 + 1;
                uint32_t bh[4], bl[4];
                ldm_x4(bh, stv + G2_BH + rb);
                ldm_x4(bl, stv + G2_BL + rb);
#pragma unroll
                for (int i = 0; i < 2; i++) {
                    mma_f16(acc[i][j0], a[i], bh[0], bh[1]);
                    mma_f16(acc[i][j1], a[i], bh[2], bh[3]);
                    mma_f16(acc[i][j0], a[i], bl[0], bl[1]);
                    mma_f16(acc[i][j1], a[i], bl[2], bl[3]);
                }
            }
        }
    }

#pragma unroll
    for (int i = 0; i < 2; i++)
#pragma unroll
        for (int j = 0; j < 4; j++) {
            int m = wm + i * 16 + gr;
            int n = wn + j * 8 + gc2;
#pragma unroll
            for (int half = 0; half < 2; half++) {
                int mm = m + half * 8;
                float2 v = make_float2(acc[i][j][half * 2 + 0], acc[i][j][half * 2 + 1]);
                *(float2*)(g_y + (size_t)(row0 + mm) * DIM + n0 + n) = v;
            }
        }
}

// ---------------- launch 5: combine ----------------
__global__ void combine_kernel(float* __restrict__ out) {
    int idx = blockIdx.x * blockDim.x + threadIdx.x;
    if (idx >= T_TOK * DIM / 4) return;
    int t = idx / (DIM / 4);
    int d4 = idx - t * (DIM / 4);
    float w0 = g_gwt[t * 2 + 0], w1 = g_gwt[t * 2 + 1];
    const float4 y0 = *(const float4*)(g_y + (size_t)g_rowOf[t * 2 + 0] * DIM + d4 * 4);
    const float4 y1 = *(const float4*)(g_y + (size_t)g_rowOf[t * 2 + 1] * DIM + d4 * 4);
    float4 o;
    o.x = w0 * y0.x + w1 * y1.x;
    o.y = w0 * y0.y + w1 * y1.y;
    o.z = w0 * y0.z + w1 * y1.z;
    o.w = w0 * y0.w + w1 * y1.w;
    ((float4*)out)[idx] = o;
}

// ---------------- launch ----------------
extern "C" void kernel_launch(void* const* d_in, const int* in_sizes, int n_in,
                              void* d_out, int out_size) {
    const float* x  = (const float*)d_in[0];
    const float* gw = (const float*)d_in[1];
    const float* w1 = (const float*)d_in[2];
    const float* w3 = (const float*)d_in[3];
    const float* w2 = (const float*)d_in[4];
    float* out = (float*)d_out;

    cudaFuncSetAttribute(gemm1_mma, cudaFuncAttributeMaxDynamicSharedMemorySize, G1_SMEM);
    cudaFuncSetAttribute(gemm2_mma, cudaFuncAttributeMaxDynamicSharedMemorySize, G2_SMEM);

    gating_kernel<<<T_TOK / 8, 256>>>(x, gw);                          // 0
    scatscan_kernel<<<1, 1024>>>();                                    // 1
    prep_kernel<<<PADT + WBLK, 256>>>(x, w1, w3, w2);                  // 2
    gemm1_mma<<<dim3(HID / 64, ROWB), 256, G1_SMEM>>>();               // 3 (ncu -s 5 target)
    gemm2_mma<<<dim3(DIM / 64, ROWB), 256, G2_SMEM>>>();               // 4
    combine_kernel<<<(T_TOK * DIM / 4 + 255) / 256, 256>>>(out);       // 5
}

// round 11
// speedup vs baseline: 1.7047x; 1.7047x over previous
#include <cuda_runtime.h>
#include <cuda_fp16.h>
#include <math.h>
#include <stdint.h>

// ---------------- problem constants ----------------
#define T_TOK 16384
#define DIM   1024
#define HID   2048
#define NEXP  8
#define TOPK  2
#define NSLOT (T_TOK*TOPK)                 // 32768
#define PADT  (NSLOT + NEXP*128)           // 33792 padded rows
#define ROWB  (PADT/128)                   // 264 row-blocks

// ---------------- device scratch (allocation-free rule) ----------------
__device__ int   g_counts[NEXP];
__device__ int   g_cntpad[NEXP];
__device__ int   g_offsets[NEXP];
__device__ int   g_perm[PADT];
__device__ int   g_rowOf[NSLOT];
__device__ int   g_sel[NSLOT];
__device__ float g_gwt[NSLOT];

// fp16 weight hi/lo splits; fp16 activations (single)
__device__ __half g_w1h[(size_t)NEXP*HID*DIM];
__device__ __half g_w1l[(size_t)NEXP*HID*DIM];
__device__ __half g_w3h[(size_t)NEXP*HID*DIM];
__device__ __half g_w3l[(size_t)NEXP*HID*DIM];
__device__ __half g_w2h[(size_t)NEXP*DIM*HID];
__device__ __half g_w2l[(size_t)NEXP*DIM*HID];
__device__ __half g_x [(size_t)PADT*DIM];
__device__ __half g_h [(size_t)PADT*HID];
__device__ float  g_y [(size_t)PADT*DIM];

// ---------------- helpers (base-PTX only) ----------------
__device__ __forceinline__ uint32_t smem_u32(const void* p) {
    uint32_t a;
    asm("{ .reg .u64 t; cvta.to.shared.u64 t, %1; cvt.u32.u64 %0, t; }" : "=r"(a) : "l"(p));
    return a;
}
__device__ __forceinline__ void cp16(uint32_t dst, const void* src) {
    asm volatile("cp.async.cg.shared.global [%0], [%1], 16;" :: "r"(dst), "l"(src));
}
__device__ __forceinline__ void cp_commit() {
    asm volatile("cp.async.commit_group;");
}
__device__ __forceinline__ void cp_wait0() {
    asm volatile("cp.async.wait_group 0;" ::: "memory");
}
// m16n8k16 row.col fp16 -> f32 accum (base PTX)
__device__ __forceinline__ void mma_f16(float c[4], const uint32_t a[4],
                                        uint32_t b0, uint32_t b1) {
    asm volatile(
        "mma.sync.aligned.m16n8k16.row.col.f32.f16.f16.f32 "
        "{%0,%1,%2,%3}, {%4,%5,%6,%7}, {%8,%9}, {%0,%1,%2,%3};"
        : "+f"(c[0]), "+f"(c[1]), "+f"(c[2]), "+f"(c[3])
        : "r"(a[0]), "r"(a[1]), "r"(a[2]), "r"(a[3]), "r"(b0), "r"(b1));
}
__device__ __forceinline__ void ldm_x4(uint32_t* r, uint32_t a) {
    asm volatile("ldmatrix.sync.aligned.m8n8.x4.shared.b16 {%0,%1,%2,%3}, [%4];"
                 : "=r"(r[0]), "=r"(r[1]), "=r"(r[2]), "=r"(r[3]) : "r"(a));
}
__device__ __forceinline__ int expert_of(int row0) {
    int e = 0;
#pragma unroll
    for (int i = 1; i < NEXP; i++) if (row0 >= g_offsets[i]) e = i;
    return e;
}

// ---------------- launch 0: gating (1 warp / token) ------
__global__ void gating_kernel(const float* __restrict__ x, const float* __restrict__ gw) {
    int t = (blockIdx.x * blockDim.x + threadIdx.x) >> 5;
    int lane = threadIdx.x & 31;
    if (t >= T_TOK) return;
    const float* xr = x + (size_t)t * DIM;
    float xv[DIM / 32];
#pragma unroll
    for (int i = 0; i < DIM / 32; i++) xv[i] = xr[lane + 32 * i];
    float logits[NEXP];
#pragma unroll
    for (int e = 0; e < NEXP; e++) {
        const float* g = gw + e * DIM;
        float acc = 0.f;
#pragma unroll
        for (int i = 0; i < DIM / 32; i++) acc = fmaf(xv[i], g[lane + 32 * i], acc);
#pragma unroll
        for (int o = 16; o; o >>= 1) acc += __shfl_xor_sync(0xffffffffu, acc, o);
        logits[e] = acc;
    }
    if (lane == 0) {
        int e0 = 0; float l0 = logits[0];
#pragma unroll
        for (int e = 1; e < NEXP; e++) if (logits[e] > l0) { l0 = logits[e]; e0 = e; }
        int e1 = (e0 == 0) ? 1 : 0; float l1 = logits[e1];
#pragma unroll
        for (int e = 0; e < NEXP; e++) if (e != e0 && logits[e] > l1) { l1 = logits[e]; e1 = e; }
        float p1 = __expf(l1 - l0);
        float inv = 1.f / (1.f + p1);
        g_sel[t * 2 + 0] = e0; g_sel[t * 2 + 1] = e1;
        g_gwt[t * 2 + 0] = inv; g_gwt[t * 2 + 1] = p1 * inv;
    }
}

// ---------------- launch 1: count + scan + scatter (single block) -----------
__global__ __launch_bounds__(1024) void scatscan_kernel() {
    __shared__ int scnt[NEXP];
    __shared__ int scur[NEXP];
    int tid = threadIdx.x;
    if (tid < NEXP) scnt[tid] = 0;
    __syncthreads();
    for (int idx = tid; idx < NSLOT; idx += 1024)
        atomicAdd(&scnt[g_sel[idx]], 1);
    __syncthreads();
    if (tid == 0) {
        int o = 0;
        for (int e = 0; e < NEXP; e++) {
            int c = scnt[e];
            int cp = (c + 127) & ~127;
            g_counts[e] = c;
            g_offsets[e] = o;
            g_cntpad[e] = cp;
            scur[e] = o;
            o += cp;
        }
    }
    __syncthreads();
    for (int idx = tid; idx < NSLOT; idx += 1024) {
        int e = g_sel[idx];
        int pos = atomicAdd(&scur[e], 1);
        g_perm[pos] = idx >> 1;
        g_rowOf[idx] = pos;
    }
}

// ---------------- launch 2: prep = gather(x->fp16) + weight hi/lo fp16 ------
#define WQ ((size_t)NEXP*HID*DIM/4)
#define WBLK ((unsigned)((3*WQ + 255) / 256))
__global__ __launch_bounds__(256) void prep_kernel(const float* __restrict__ x,
                                                   const float* __restrict__ w1,
                                                   const float* __restrict__ w3,
                                                   const float* __restrict__ w2) {
    int b = blockIdx.x;
    if (b < PADT) {
        int row = b;
        int e = -1, r = 0;
#pragma unroll
        for (int i = 0; i < NEXP; i++) {
            int o = g_offsets[i], c = g_cntpad[i];
            if (row >= o && row < o + c) { e = i; r = row - o; }
        }
        if (e < 0) return;
        float4 v = make_float4(0.f, 0.f, 0.f, 0.f);
        if (r < g_counts[e]) {
            int tok = g_perm[row];
            v = *(const float4*)(x + (size_t)tok * DIM + threadIdx.x * 4);
        }
        size_t o = (size_t)row * DIM + threadIdx.x * 4;
        __half2 a0, a1;
        a0.x = __float2half_rn(v.x); a0.y = __float2half_rn(v.y);
        a1.x = __float2half_rn(v.z); a1.y = __float2half_rn(v.w);
        ((__half2*)(g_x + o))[0] = a0;
        ((__half2*)(g_x + o))[1] = a1;
    } else {
        size_t i = (size_t)(b - PADT) * 256 + threadIdx.x;
        if (i >= 3 * WQ) return;
        const float* src; __half *hi, *lo; size_t j;
        if (i < WQ)          { src = w1; hi = g_w1h; lo = g_w1l; j = i; }
        else if (i < 2 * WQ) { src = w3; hi = g_w3h; lo = g_w3l; j = i - WQ; }
        else                 { src = w2; hi = g_w2h; lo = g_w2l; j = i - 2 * WQ; }
        float4 v = ((const float4*)src)[j];
        __half2 h0, h1, l0, l1;
        h0.x = __float2half_rn(v.x); h0.y = __float2half_rn(v.y);
        h1.x = __float2half_rn(v.z); h1.y = __float2half_rn(v.w);
        l0.x = __float2half_rn(v.x - __half2float(h0.x));
        l0.y = __float2half_rn(v.y - __half2float(h0.y));
        l1.x = __float2half_rn(v.z - __half2float(h1.x));
        l1.y = __float2half_rn(v.w - __half2float(h1.y));
        ((__half2*)(hi + 4 * j))[0] = h0;
        ((__half2*)(hi + 4 * j))[1] = h1;
        ((__half2*)(lo + 4 * j))[0] = l0;
        ((__half2*)(lo + 4 * j))[1] = l1;
    }
}

// ---------------- shared memory layouts (K-chunk = 64 halves = 128 B) -------
#define SAW 144    // 128B data + 16B pad per row: 16B aligned, conflict-free
// GEMM1: A [128x64], B1/B3 hi/lo [64x64]
#define G1_A   0
#define G1_B1H 18432
#define G1_B1L 27648
#define G1_B3H 36864
#define G1_B3L 46080
#define G1_STAGE 55296
#define G1_SMEM (2*G1_STAGE)    // 110592/CTA, 2 CTAs = 216 KB
// GEMM2: A [128x64], B hi/lo [64x64]
#define G2_A   0
#define G2_BH  18432
#define G2_BL  27648
#define G2_STAGE 36864
#define G2_SMEM (2*G2_STAGE)

// ---------------- GEMM1: hidden = silu(x@w1^T) * (x@w3^T), fp16 2-pass ------
__device__ __forceinline__ void g1_load(uint32_t st,
        const __half* A,
        const __half* B1h, const __half* B1l,
        const __half* B3h, const __half* B3l, int kt, int tid) {
    // A: 128 rows x 128B = 1024 chunks -> 4/thread
#pragma unroll
    for (int i = 0; i < 4; i++) {
        int idx = tid + i * 256;
        int m = idx >> 3, c = idx & 7;
        cp16(st + G1_A + m * SAW + c * 16, A + (size_t)m * DIM + kt + c * 8);
    }
    // each B tile: 64 rows x 128B = 512 chunks -> 2/thread
#pragma unroll
    for (int i = 0; i < 2; i++) {
        int idx = tid + i * 256;
        int n = idx >> 3, c = idx & 7;
        cp16(st + G1_B1H + n * SAW + c * 16, B1h + (size_t)n * DIM + kt + c * 8);
        cp16(st + G1_B1L + n * SAW + c * 16, B1l + (size_t)n * DIM + kt + c * 8);
        cp16(st + G1_B3H + n * SAW + c * 16, B3h + (size_t)n * DIM + kt + c * 8);
        cp16(st + G1_B3L + n * SAW + c * 16, B3l + (size_t)n * DIM + kt + c * 8);
    }
}

__global__ __launch_bounds__(256, 2) void gemm1_mma() {
    int row0 = blockIdx.y * 128;
    if (row0 >= g_offsets[NEXP - 1] + g_cntpad[NEXP - 1]) return;
    int e = expert_of(row0);
    int n0 = blockIdx.x * 64;

    extern __shared__ __align__(16) char smem[];
    uint32_t sb = smem_u32(smem);
    int tid = threadIdx.x, lane = tid & 31, warp = tid >> 5;
    int gr = lane >> 2, gc2 = (lane & 3) * 2;
    int wm = (warp & 3) * 32;
    int wn = (warp >> 2) * 32;

    const __half* A   = g_x + (size_t)row0 * DIM;
    const size_t wb = ((size_t)e * HID + n0) * DIM;
    const __half* B1h = g_w1h + wb;
    const __half* B1l = g_w1l + wb;
    const __half* B3h = g_w3h + wb;
    const __half* B3l = g_w3l + wb;

    float acc1[2][4][4], acc3[2][4][4];
#pragma unroll
    for (int i = 0; i < 2; i++)
#pragma unroll
        for (int j = 0; j < 4; j++)
#pragma unroll
            for (int q = 0; q < 4; q++) { acc1[i][j][q] = 0.f; acc3[i][j][q] = 0.f; }

    uint32_t aAddr = (lane & 15) * SAW + (lane >> 4) * 16;
    uint32_t bAddr = (((lane >> 4) & 1) * 8 + (lane & 7)) * SAW + ((lane >> 3) & 1) * 16;

    const int NK = DIM / 64;   // 16
    g1_load(sb, A, B1h, B1l, B3h, B3l, 0, tid);
    cp_commit();

#pragma unroll 1
    for (int kc = 0; kc < NK; kc++) {
        cp_wait0();
        __syncthreads();
        if (kc + 1 < NK) {
            g1_load(sb + ((kc + 1) & 1) * G1_STAGE, A, B1h, B1l, B3h, B3l,
                    (kc + 1) * 64, tid);
            cp_commit();
        }
        uint32_t stv = sb + (kc & 1) * G1_STAGE;
#pragma unroll
        for (int ks = 0; ks < 4; ks++) {
            uint32_t k0b = ks * 32;
            uint32_t a[2][4];
#pragma unroll
            for (int i = 0; i < 2; i++)
                ldm_x4(a[i], stv + G1_A + (wm + i * 16) * SAW + aAddr + k0b);
#pragma unroll
            for (int jp = 0; jp < 2; jp++) {
                uint32_t rb = (wn + jp * 16) * SAW + bAddr + k0b;
                int j0 = jp * 2, j1 = jp * 2 + 1;
                uint32_t bh[4], bl[4];
                ldm_x4(bh, stv + G1_B1H + rb);
                ldm_x4(bl, stv + G1_B1L + rb);
#pragma unroll
                for (int i = 0; i < 2; i++) {
                    mma_f16(acc1[i][j0], a[i], bh[0], bh[1]);
                    mma_f16(acc1[i][j1], a[i], bh[2], bh[3]);
                    mma_f16(acc1[i][j0], a[i], bl[0], bl[1]);
                    mma_f16(acc1[i][j1], a[i], bl[2], bl[3]);
                }
                ldm_x4(bh, stv + G1_B3H + rb);
                ldm_x4(bl, stv + G1_B3L + rb);
#pragma unroll
                for (int i = 0; i < 2; i++) {
                    mma_f16(acc3[i][j0], a[i], bh[0], bh[1]);
                    mma_f16(acc3[i][j1], a[i], bh[2], bh[3]);
                    mma_f16(acc3[i][j0], a[i], bl[0], bl[1]);
                    mma_f16(acc3[i][j1], a[i], bl[2], bl[3]);
                }
            }
        }
    }

    // epilogue: silu(h1)*h3 -> fp16 hidden
#pragma unroll
    for (int i = 0; i < 2; i++)
#pragma unroll
        for (int j = 0; j < 4; j++) {
            int m = wm + i * 16 + gr;
            int n = wn + j * 8 + gc2;
#pragma unroll
            for (int half = 0; half < 2; half++) {
                int mm = m + half * 8;
                float h1a = acc1[i][j][half * 2 + 0], h1b = acc1[i][j][half * 2 + 1];
                float h3a = acc3[i][j][half * 2 + 0], h3b = acc3[i][j][half * 2 + 1];
                float v0 = h3a * h1a / (1.f + __expf(-h1a));
                float v1 = h3b * h1b / (1.f + __expf(-h1b));
                __half2 hv;
                hv.x = __float2half_rn(v0);
                hv.y = __float2half_rn(v1);
                *(__half2*)(g_h + (size_t)(row0 + mm) * HID + n0 + n) = hv;
            }
        }
}

// ---------------- GEMM2: y = hidden @ w2^T, fp16 2-pass, tile 128x64 --------
__device__ __forceinline__ void g2_load(uint32_t st,
        const __half* A, const __half* Bh, const __half* Bl, int kt, int tid) {
#pragma unroll
    for (int i = 0; i < 4; i++) {
        int idx = tid + i * 256;
        int m = idx >> 3, c = idx & 7;
        cp16(st + G2_A + m * SAW + c * 16, A + (size_t)m * HID + kt + c * 8);
    }
#pragma unroll
    for (int i = 0; i < 2; i++) {
        int idx = tid + i * 256;
        int n = idx >> 3, c = idx & 7;
        cp16(st + G2_BH + n * SAW + c * 16, Bh + (size_t)n * HID + kt + c * 8);
        cp16(st + G2_BL + n * SAW + c * 16, Bl + (size_t)n * HID + kt + c * 8);
    }
}

__global__ __launch_bounds__(256, 2) void gemm2_mma() {
    int row0 = blockIdx.y * 128;
    if (row0 >= g_offsets[NEXP - 1] + g_cntpad[NEXP - 1]) return;
    int e = expert_of(row0);
    int n0 = blockIdx.x * 64;

    extern __shared__ __align__(16) char smem[];
    uint32_t sb = smem_u32(smem);
    int tid = threadIdx.x, lane = tid & 31, warp = tid >> 5;
    int gr = lane >> 2, gc2 = (lane & 3) * 2;
    int wm = (warp & 3) * 32;
    int wn = (warp >> 2) * 32;

    const __half* A  = g_h + (size_t)row0 * HID;
    const size_t wb = ((size_t)e * DIM + n0) * HID;
    const __half* Bh = g_w2h + wb;
    const __half* Bl = g_w2l + wb;

    float acc[2][4][4];
#pragma unroll
    for (int i = 0; i < 2; i++)
#pragma unroll
        for (int j = 0; j < 4; j++)
#pragma unroll
            for (int q = 0; q < 4; q++) acc[i][j][q] = 0.f;

    uint32_t aAddr = (lane & 15) * SAW + (lane >> 4) * 16;
    uint32_t bAddr = (((lane >> 4) & 1) * 8 + (lane & 7)) * SAW + ((lane >> 3) & 1) * 16;

    const int NK = HID / 64;   // 32
    g2_load(sb, A, Bh, Bl, 0, tid);
    cp_commit();

#pragma unroll 1
    for (int kc = 0; kc < NK; kc++) {
        cp_wait0();
        __syncthreads();
        if (kc + 1 < NK) {
            g2_load(sb + ((kc + 1) & 1) * G2_STAGE, A, Bh, Bl, (kc + 1) * 64, tid);
            cp_commit();
        }
        uint32_t stv = sb + (kc & 1) * G2_STAGE;
#pragma unroll
        for (int ks = 0; ks < 4; ks++) {
            uint32_t k0b = ks * 32;
            uint32_t a[2][4];
#pragma unroll
            for (int i = 0; i < 2; i++)
                ldm_x4(a[i], stv + G2_A + (wm + i * 16) * SAW + aAddr + k0b);
#pragma unroll
            for (int jp = 0; jp < 2; jp++) {
                uint32_t rb = (wn + jp * 16) * SAW + bAddr + k0b;
                int j0 = jp * 2, j1 = jp * 2 + 1;
                uint32_t bh[4], bl[4];
                ldm_x4(bh, stv + G2_BH + rb);
                ldm_x4(bl, stv + G2_BL + rb);
#pragma unroll
                for (int i = 0; i < 2; i++) {
                    mma_f16(acc[i][j0], a[i], bh[0], bh[1]);
                    mma_f16(acc[i][j1], a[i], bh[2], bh[3]);
                    mma_f16(acc[i][j0], a[i], bl[0], bl[1]);
                    mma_f16(acc[i][j1], a[i], bl[2], bl[3]);
                }
            }
        }
    }

#pragma unroll
    for (int i = 0; i < 2; i++)
#pragma unroll
        for (int j = 0; j < 4; j++) {
            int m = wm + i * 16 + gr;
            int n = wn + j * 8 + gc2;
#pragma unroll
            for (int half = 0; half < 2; half++) {
                int mm = m + half * 8;
                float2 v = make_float2(acc[i][j][half * 2 + 0], acc[i][j][half * 2 + 1]);
                *(float2*)(g_y + (size_t)(row0 + mm) * DIM + n0 + n) = v;
            }
        }
}

// ---------------- launch 5: combine ----------------
__global__ void combine_kernel(float* __restrict__ out) {
    int idx = blockIdx.x * blockDim.x + threadIdx.x;
    if (idx >= T_TOK * DIM / 4) return;
    int t = idx / (DIM / 4);
    int d4 = idx - t * (DIM / 4);
    float w0 = g_gwt[t * 2 + 0], w1 = g_gwt[t * 2 + 1];
    const float4 y0 = *(const float4*)(g_y + (size_t)g_rowOf[t * 2 + 0] * DIM + d4 * 4);
    const float4 y1 = *(const float4*)(g_y + (size_t)g_rowOf[t * 2 + 1] * DIM + d4 * 4);
    float4 o;
    o.x = w0 * y0.x + w1 * y1.x;
    o.y = w0 * y0.y + w1 * y1.y;
    o.z = w0 * y0.z + w1 * y1.z;
    o.w = w0 * y0.w + w1 * y1.w;
    ((float4*)out)[idx] = o;
}

// ---------------- launch ----------------
extern "C" void kernel_launch(void* const* d_in, const int* in_sizes, int n_in,
                              void* d_out, int out_size) {
    const float* x  = (const float*)d_in[0];
    const float* gw = (const float*)d_in[1];
    const float* w1 = (const float*)d_in[2];
    const float* w3 = (const float*)d_in[3];
    const float* w2 = (const float*)d_in[4];
    float* out = (float*)d_out;

    cudaFuncSetAttribute(gemm1_mma, cudaFuncAttributeMaxDynamicSharedMemorySize, G1_SMEM);
    cudaFuncSetAttribute(gemm2_mma, cudaFuncAttributeMaxDynamicSharedMemorySize, G2_SMEM);

    gating_kernel<<<T_TOK / 8, 256>>>(x, gw);                          // 0
    scatscan_kernel<<<1, 1024>>>();                                    // 1
    prep_kernel<<<PADT + WBLK, 256>>>(x, w1, w3, w2);                  // 2
    gemm1_mma<<<dim3(HID / 64, ROWB), 256, G1_SMEM>>>();               // 3 (ncu -s 5 target)
    gemm2_mma<<<dim3(DIM / 64, ROWB), 256, G2_SMEM>>>();               // 4
    combine_kernel<<<(T_TOK * DIM / 4 + 255) / 256, 256>>>(out);       // 5
}

// round 12
// speedup vs baseline: 1.7048x; 1.0001x over previous
#include <cuda_runtime.h>
#include <cuda_fp16.h>
#include <math.h>
#include <stdint.h>

// ---------------- problem constants ----------------
#define T_TOK 16384
#define DIM   1024
#define HID   2048
#define NEXP  8
#define TOPK  2
#define NSLOT (T_TOK*TOPK)                 // 32768
#define PADT  (NSLOT + NEXP*128)           // 33792 padded rows
#define ROWB  (PADT/128)                   // 264 row-blocks

// ---------------- device scratch (allocation-free rule) ----------------
__device__ int   g_counts[NEXP];
__device__ int   g_cntpad[NEXP];
__device__ int   g_offsets[NEXP];
__device__ int   g_perm[PADT];
__device__ int   g_rowOf[NSLOT];
__device__ int   g_sel[NSLOT];
__device__ float g_gwt[NSLOT];

// fp16 weight hi/lo splits; fp16 activations (single)
__device__ __half g_w1h[(size_t)NEXP*HID*DIM];
__device__ __half g_w1l[(size_t)NEXP*HID*DIM];
__device__ __half g_w3h[(size_t)NEXP*HID*DIM];
__device__ __half g_w3l[(size_t)NEXP*HID*DIM];
__device__ __half g_w2h[(size_t)NEXP*DIM*HID];
__device__ __half g_w2l[(size_t)NEXP*DIM*HID];
__device__ __half g_x [(size_t)PADT*DIM];
__device__ __half g_h [(size_t)PADT*HID];
__device__ float  g_y [(size_t)PADT*DIM];

// ---------------- helpers (base-PTX only) ----------------
__device__ __forceinline__ uint32_t smem_u32(const void* p) {
    uint32_t a;
    asm("{ .reg .u64 t; cvta.to.shared.u64 t, %1; cvt.u32.u64 %0, t; }" : "=r"(a) : "l"(p));
    return a;
}
__device__ __forceinline__ void cp16(uint32_t dst, const void* src) {
    asm volatile("cp.async.cg.shared.global [%0], [%1], 16;" :: "r"(dst), "l"(src));
}
__device__ __forceinline__ void cp_commit() {
    asm volatile("cp.async.commit_group;");
}
__device__ __forceinline__ void cp_wait0() {
    asm volatile("cp.async.wait_group 0;" ::: "memory");
}
// m16n8k16 row.col fp16 -> f32 accum (base PTX)
__device__ __forceinline__ void mma_f16(float c[4], const uint32_t a[4],
                                        uint32_t b0, uint32_t b1) {
    asm volatile(
        "mma.sync.aligned.m16n8k16.row.col.f32.f16.f16.f32 "
        "{%0,%1,%2,%3}, {%4,%5,%6,%7}, {%8,%9}, {%0,%1,%2,%3};"
        : "+f"(c[0]), "+f"(c[1]), "+f"(c[2]), "+f"(c[3])
        : "r"(a[0]), "r"(a[1]), "r"(a[2]), "r"(a[3]), "r"(b0), "r"(b1));
}
__device__ __forceinline__ void ldm_x4(uint32_t* r, uint32_t a) {
    asm volatile("ldmatrix.sync.aligned.m8n8.x4.shared.b16 {%0,%1,%2,%3}, [%4];"
                 : "=r"(r[0]), "=r"(r[1]), "=r"(r[2]), "=r"(r[3]) : "r"(a));
}
__device__ __forceinline__ int expert_of(int row0) {
    int e = 0;
#pragma unroll
    for (int i = 1; i < NEXP; i++) if (row0 >= g_offsets[i]) e = i;
    return e;
}

// ---------------- launch 0: gating (1 warp / token) ------
__global__ void gating_kernel(const float* __restrict__ x, const float* __restrict__ gw) {
    int t = (blockIdx.x * blockDim.x + threadIdx.x) >> 5;
    int lane = threadIdx.x & 31;
    if (t >= T_TOK) return;
    const float* xr = x + (size_t)t * DIM;
    float xv[DIM / 32];
#pragma unroll
    for (int i = 0; i < DIM / 32; i++) xv[i] = xr[lane + 32 * i];
    float logits[NEXP];
#pragma unroll
    for (int e = 0; e < NEXP; e++) {
        const float* g = gw + e * DIM;
        float acc = 0.f;
#pragma unroll
        for (int i = 0; i < DIM / 32; i++) acc = fmaf(xv[i], g[lane + 32 * i], acc);
#pragma unroll
        for (int o = 16; o; o >>= 1) acc += __shfl_xor_sync(0xffffffffu, acc, o);
        logits[e] = acc;
    }
    if (lane == 0) {
        int e0 = 0; float l0 = logits[0];
#pragma unroll
        for (int e = 1; e < NEXP; e++) if (logits[e] > l0) { l0 = logits[e]; e0 = e; }
        int e1 = (e0 == 0) ? 1 : 0; float l1 = logits[e1];
#pragma unroll
        for (int e = 0; e < NEXP; e++) if (e != e0 && logits[e] > l1) { l1 = logits[e]; e1 = e; }
        float p1 = __expf(l1 - l0);
        float inv = 1.f / (1.f + p1);
        g_sel[t * 2 + 0] = e0; g_sel[t * 2 + 1] = e1;
        g_gwt[t * 2 + 0] = inv; g_gwt[t * 2 + 1] = p1 * inv;
    }
}

// ---------------- launch 1: count + scan + scatter (single block) -----------
__global__ __launch_bounds__(1024) void scatscan_kernel() {
    __shared__ int scnt[NEXP];
    __shared__ int scur[NEXP];
    int tid = threadIdx.x;
    if (tid < NEXP) scnt[tid] = 0;
    __syncthreads();
    for (int idx = tid; idx < NSLOT; idx += 1024)
        atomicAdd(&scnt[g_sel[idx]], 1);
    __syncthreads();
    if (tid == 0) {
        int o = 0;
        for (int e = 0; e < NEXP; e++) {
            int c = scnt[e];
            int cp = (c + 127) & ~127;
            g_counts[e] = c;
            g_offsets[e] = o;
            g_cntpad[e] = cp;
            scur[e] = o;
            o += cp;
        }
    }
    __syncthreads();
    for (int idx = tid; idx < NSLOT; idx += 1024) {
        int e = g_sel[idx];
        int pos = atomicAdd(&scur[e], 1);
        g_perm[pos] = idx >> 1;
        g_rowOf[idx] = pos;
    }
}

// ---------------- launch 2: prep = gather(x->fp16) + weight hi/lo fp16 ------
#define WQ ((size_t)NEXP*HID*DIM/4)
#define WBLK ((unsigned)((3*WQ + 255) / 256))
__global__ __launch_bounds__(256) void prep_kernel(const float* __restrict__ x,
                                                   const float* __restrict__ w1,
                                                   const float* __restrict__ w3,
                                                   const float* __restrict__ w2) {
    int b = blockIdx.x;
    if (b < PADT) {
        int row = b;
        int e = -1, r = 0;
#pragma unroll
        for (int i = 0; i < NEXP; i++) {
            int o = g_offsets[i], c = g_cntpad[i];
            if (row >= o && row < o + c) { e = i; r = row - o; }
        }
        if (e < 0) return;
        float4 v = make_float4(0.f, 0.f, 0.f, 0.f);
        if (r < g_counts[e]) {
            int tok = g_perm[row];
            v = *(const float4*)(x + (size_t)tok * DIM + threadIdx.x * 4);
        }
        size_t o = (size_t)row * DIM + threadIdx.x * 4;
        __half2 a0, a1;
        a0.x = __float2half_rn(v.x); a0.y = __float2half_rn(v.y);
        a1.x = __float2half_rn(v.z); a1.y = __float2half_rn(v.w);
        ((__half2*)(g_x + o))[0] = a0;
        ((__half2*)(g_x + o))[1] = a1;
    } else {
        size_t i = (size_t)(b - PADT) * 256 + threadIdx.x;
        if (i >= 3 * WQ) return;
        const float* src; __half *hi, *lo; size_t j;
        if (i < WQ)          { src = w1; hi = g_w1h; lo = g_w1l; j = i; }
        else if (i < 2 * WQ) { src = w3; hi = g_w3h; lo = g_w3l; j = i - WQ; }
        else                 { src = w2; hi = g_w2h; lo = g_w2l; j = i - 2 * WQ; }
        float4 v = ((const float4*)src)[j];
        __half2 h0, h1, l0, l1;
        h0.x = __float2half_rn(v.x); h0.y = __float2half_rn(v.y);
        h1.x = __float2half_rn(v.z); h1.y = __float2half_rn(v.w);
        l0.x = __float2half_rn(v.x - __half2float(h0.x));
        l0.y = __float2half_rn(v.y - __half2float(h0.y));
        l1.x = __float2half_rn(v.z - __half2float(h1.x));
        l1.y = __float2half_rn(v.w - __half2float(h1.y));
        ((__half2*)(hi + 4 * j))[0] = h0;
        ((__half2*)(hi + 4 * j))[1] = h1;
        ((__half2*)(lo + 4 * j))[0] = l0;
        ((__half2*)(lo + 4 * j))[1] = l1;
    }
}

// ---------------- shared memory layouts (K-chunk = 64 halves = 128 B) -------
#define SAW 144    // 128B data + 16B pad per row: 16B aligned, conflict-free
// GEMM1: A [128x64], B1/B3 hi/lo [64x64]
#define G1_A   0
#define G1_B1H 18432
#define G1_B1L 27648
#define G1_B3H 36864
#define G1_B3L 46080
#define G1_STAGE 55296
#define G1_SMEM (2*G1_STAGE)    // 110592/CTA, 2 CTAs = 216 KB
// GEMM2: A [128x64], B hi/lo [64x64]
#define G2_A   0
#define G2_BH  18432
#define G2_BL  27648
#define G2_STAGE 36864
#define G2_SMEM (2*G2_STAGE)

// ---------------- GEMM1: hidden = silu(x@w1^T) * (x@w3^T), fp16 2-pass ------
__device__ __forceinline__ void g1_load(uint32_t st,
        const __half* A,
        const __half* B1h, const __half* B1l,
        const __half* B3h, const __half* B3l, int kt, int tid) {
    // A: 128 rows x 128B = 1024 chunks -> 4/thread
#pragma unroll
    for (int i = 0; i < 4; i++) {
        int idx = tid + i * 256;
        int m = idx >> 3, c = idx & 7;
        cp16(st + G1_A + m * SAW + c * 16, A + (size_t)m * DIM + kt + c * 8);
    }
    // each B tile: 64 rows x 128B = 512 chunks -> 2/thread
#pragma unroll
    for (int i = 0; i < 2; i++) {
        int idx = tid + i * 256;
        int n = idx >> 3, c = idx & 7;
        cp16(st + G1_B1H + n * SAW + c * 16, B1h + (size_t)n * DIM + kt + c * 8);
        cp16(st + G1_B1L + n * SAW + c * 16, B1l + (size_t)n * DIM + kt + c * 8);
        cp16(st + G1_B3H + n * SAW + c * 16, B3h + (size_t)n * DIM + kt + c * 8);
        cp16(st + G1_B3L + n * SAW + c * 16, B3l + (size_t)n * DIM + kt + c * 8);
    }
}

__global__ __launch_bounds__(256, 2) void gemm1_mma() {
    int row0 = blockIdx.y * 128;
    if (row0 >= g_offsets[NEXP - 1] + g_cntpad[NEXP - 1]) return;
    int e = expert_of(row0);
    int n0 = blockIdx.x * 64;

    extern __shared__ __align__(16) char smem[];
    uint32_t sb = smem_u32(smem);
    int tid = threadIdx.x, lane = tid & 31, warp = tid >> 5;
    int gr = lane >> 2, gc2 = (lane & 3) * 2;
    int wm = (warp & 3) * 32;
    int wn = (warp >> 2) * 32;

    const __half* A   = g_x + (size_t)row0 * DIM;
    const size_t wb = ((size_t)e * HID + n0) * DIM;
    const __half* B1h = g_w1h + wb;
    const __half* B1l = g_w1l + wb;
    const __half* B3h = g_w3h + wb;
    const __half* B3l = g_w3l + wb;

    float acc1[2][4][4], acc3[2][4][4];
#pragma unroll
    for (int i = 0; i < 2; i++)
#pragma unroll
        for (int j = 0; j < 4; j++)
#pragma unroll
            for (int q = 0; q < 4; q++) { acc1[i][j][q] = 0.f; acc3[i][j][q] = 0.f; }

    uint32_t aAddr = (lane & 15) * SAW + (lane >> 4) * 16;
    uint32_t bAddr = (((lane >> 4) & 1) * 8 + (lane & 7)) * SAW + ((lane >> 3) & 1) * 16;

    const int NK = DIM / 64;   // 16
    g1_load(sb, A, B1h, B1l, B3h, B3l, 0, tid);
    cp_commit();

#pragma unroll 1
    for (int kc = 0; kc < NK; kc++) {
        cp_wait0();
        __syncthreads();
        if (kc + 1 < NK) {
            g1_load(sb + ((kc + 1) & 1) * G1_STAGE, A, B1h, B1l, B3h, B3l,
                    (kc + 1) * 64, tid);
            cp_commit();
        }
        uint32_t stv = sb + (kc & 1) * G1_STAGE;
#pragma unroll
        for (int ks = 0; ks < 4; ks++) {
            uint32_t k0b = ks * 32;
            uint32_t a[2][4];
#pragma unroll
            for (int i = 0; i < 2; i++)
                ldm_x4(a[i], stv + G1_A + (wm + i * 16) * SAW + aAddr + k0b);
#pragma unroll
            for (int jp = 0; jp < 2; jp++) {
                uint32_t rb = (wn + jp * 16) * SAW + bAddr + k0b;
                int j0 = jp * 2, j1 = jp * 2 + 1;
                uint32_t bh[4], bl[4];
                ldm_x4(bh, stv + G1_B1H + rb);
                ldm_x4(bl, stv + G1_B1L + rb);
#pragma unroll
                for (int i = 0; i < 2; i++) {
                    mma_f16(acc1[i][j0], a[i], bh[0], bh[1]);
                    mma_f16(acc1[i][j1], a[i], bh[2], bh[3]);
                    mma_f16(acc1[i][j0], a[i], bl[0], bl[1]);
                    mma_f16(acc1[i][j1], a[i], bl[2], bl[3]);
                }
                ldm_x4(bh, stv + G1_B3H + rb);
                ldm_x4(bl, stv + G1_B3L + rb);
#pragma unroll
                for (int i = 0; i < 2; i++) {
                    mma_f16(acc3[i][j0], a[i], bh[0], bh[1]);
                    mma_f16(acc3[i][j1], a[i], bh[2], bh[3]);
                    mma_f16(acc3[i][j0], a[i], bl[0], bl[1]);
                    mma_f16(acc3[i][j1], a[i], bl[2], bl[3]);
                }
            }
        }
    }

    // epilogue: silu(h1)*h3 -> fp16 hidden
#pragma unroll
    for (int i = 0; i < 2; i++)
#pragma unroll
        for (int j = 0; j < 4; j++) {
            int m = wm + i * 16 + gr;
            int n = wn + j * 8 + gc2;
#pragma unroll
            for (int half = 0; half < 2; half++) {
                int mm = m + half * 8;
                float h1a = acc1[i][j][half * 2 + 0], h1b = acc1[i][j][half * 2 + 1];
                float h3a = acc3[i][j][half * 2 + 0], h3b = acc3[i][j][half * 2 + 1];
                float v0 = h3a * h1a / (1.f + __expf(-h1a));
                float v1 = h3b * h1b / (1.f + __expf(-h1b));
                __half2 hv;
                hv.x = __float2half_rn(v0);
                hv.y = __float2half_rn(v1);
                *(__half2*)(g_h + (size_t)(row0 + mm) * HID + n0 + n) = hv;
            }
        }
}

// ---------------- GEMM2: y = hidden @ w2^T, fp16 2-pass, tile 128x64 --------
__device__ __forceinline__ void g2_load(uint32_t st,
        const __half* A, const __half* Bh, const __half* Bl, int kt, int tid) {
#pragma unroll
    for (int i = 0; i < 4; i++) {
        int idx = tid + i * 256;
        int m = idx >> 3, c = idx & 7;
        cp16(st + G2_A + m * SAW + c * 16, A + (size_t)m * HID + kt + c * 8);
    }
#pragma unroll
    for (int i = 0; i < 2; i++) {
        int idx = tid + i * 256;
        int n = idx >> 3, c = idx & 7;
        cp16(st + G2_BH + n * SAW + c * 16, Bh + (size_t)n * HID + kt + c * 8);
        cp16(st + G2_BL + n * SAW + c * 16, Bl + (size_t)n * HID + kt + c * 8);
    }
}

__global__ __launch_bounds__(256, 2) void gemm2_mma() {
    int row0 = blockIdx.y * 128;
    if (row0 >= g_offsets[NEXP - 1] + g_cntpad[NEXP - 1]) return;
    int e = expert_of(row0);
    int n0 = blockIdx.x * 64;

    extern __shared__ __align__(16) char smem[];
    uint32_t sb = smem_u32(smem);
    int tid = threadIdx.x, lane = tid & 31, warp = tid >> 5;
    int gr = lane >> 2, gc2 = (lane & 3) * 2;
    int wm = (warp & 3) * 32;
    int wn = (warp >> 2) * 32;

    const __half* A  = g_h + (size_t)row0 * HID;
    const size_t wb = ((size_t)e * DIM + n0) * HID;
    const __half* Bh = g_w2h + wb;
    const __half* Bl = g_w2l + wb;

    float acc[2][4][4];
#pragma unroll
    for (int i = 0; i < 2; i++)
#pragma unroll
        for (int j = 0; j < 4; j++)
#pragma unroll
            for (int q = 0; q < 4; q++) acc[i][j][q] = 0.f;

    uint32_t aAddr = (lane & 15) * SAW + (lane >> 4) * 16;
    uint32_t bAddr = (((lane >> 4) & 1) * 8 + (lane & 7)) * SAW + ((lane >> 3) & 1) * 16;

    const int NK = HID / 64;   // 32
    g2_load(sb, A, Bh, Bl, 0, tid);
    cp_commit();

#pragma unroll 1
    for (int kc = 0; kc < NK; kc++) {
        cp_wait0();
        __syncthreads();
        if (kc + 1 < NK) {
            g2_load(sb + ((kc + 1) & 1) * G2_STAGE, A, Bh, Bl, (kc + 1) * 64, tid);
            cp_commit();
        }
        uint32_t stv = sb + (kc & 1) * G2_STAGE;
#pragma unroll
        for (int ks = 0; ks < 4; ks++) {
            uint32_t k0b = ks * 32;
            uint32_t a[2][4];
#pragma unroll
            for (int i = 0; i < 2; i++)
                ldm_x4(a[i], stv + G2_A + (wm + i * 16) * SAW + aAddr + k0b);
#pragma unroll
            for (int jp = 0; jp < 2; jp++) {
                uint32_t rb = (wn + jp * 16) * SAW + bAddr + k0b;
                int j0 = jp * 2, j1 = jp * 2 + 1;
                uint32_t bh[4], bl[4];
                ldm_x4(bh, stv + G2_BH + rb);
                ldm_x4(bl, stv + G2_BL + rb);
#pragma unroll
                for (int i = 0; i < 2; i++) {
                    mma_f16(acc[i][j0], a[i], bh[0], bh[1]);
                    mma_f16(acc[i][j1], a[i], bh[2], bh[3]);
                    mma_f16(acc[i][j0], a[i], bl[0], bl[1]);
                    mma_f16(acc[i][j1], a[i], bl[2], bl[3]);
                }
            }
        }
    }

#pragma unroll
    for (int i = 0; i < 2; i++)
#pragma unroll
        for (int j = 0; j < 4; j++) {
            int m = wm + i * 16 + gr;
            int n = wn + j * 8 + gc2;
#pragma unroll
            for (int half = 0; half < 2; half++) {
                int mm = m + half * 8;
                float2 v = make_float2(acc[i][j][half * 2 + 0], acc[i][j][half * 2 + 1]);
                *(float2*)(g_y + (size_t)(row0 + mm) * DIM + n0 + n) = v;
            }
        }
}

// ---------------- launch 5: combine ----------------
__global__ void combine_kernel(float* __restrict__ out) {
    int idx = blockIdx.x * blockDim.x + threadIdx.x;
    if (idx >= T_TOK * DIM / 4) return;
    int t = idx / (DIM / 4);
    int d4 = idx - t * (DIM / 4);
    float w0 = g_gwt[t * 2 + 0], w1 = g_gwt[t * 2 + 1];
    const float4 y0 = *(const float4*)(g_y + (size_t)g_rowOf[t * 2 + 0] * DIM + d4 * 4);
    const float4 y1 = *(const float4*)(g_y + (size_t)g_rowOf[t * 2 + 1] * DIM + d4 * 4);
    float4 o;
    o.x = w0 * y0.x + w1 * y1.x;
    o.y = w0 * y0.y + w1 * y1.y;
    o.z = w0 * y0.z + w1 * y1.z;
    o.w = w0 * y0.w + w1 * y1.w;
    ((float4*)out)[idx] = o;
}

// ---------------- launch ----------------
extern "C" void kernel_launch(void* const* d_in, const int* in_sizes, int n_in,
                              void* d_out, int out_size) {
    const float* x  = (const float*)d_in[0];
    const float* gw = (const float*)d_in[1];
    const float* w1 = (const float*)d_in[2];
    const float* w3 = (const float*)d_in[3];
    const float* w2 = (const float*)d_in[4];
    float* out = (float*)d_out;

    cudaFuncSetAttribute(gemm1_mma, cudaFuncAttributeMaxDynamicSharedMemorySize, G1_SMEM);
    cudaFuncSetAttribute(gemm2_mma, cudaFuncAttributeMaxDynamicSharedMemorySize, G2_SMEM);

    gating_kernel<<<T_TOK / 8, 256>>>(x, gw);                          // 0
    scatscan_kernel<<<1, 1024>>>();                                    // 1
    prep_kernel<<<PADT + WBLK, 256>>>(x, w1, w3, w2);                  // 2
    gemm1_mma<<<dim3(HID / 64, ROWB), 256, G1_SMEM>>>();               // 3 (ncu -s 5 target)
    gemm2_mma<<<dim3(DIM / 64, ROWB), 256, G2_SMEM>>>();               // 4
    combine_kernel<<<(T_TOK * DIM / 4 + 255) / 256, 256>>>(out);       // 5
}

// round 13
// speedup vs baseline: 1.7056x; 1.0005x over previous
#include <cuda_runtime.h>
#include <cuda_fp16.h>
#include <math.h>
#include <stdint.h>

// ---------------- problem constants ----------------
#define T_TOK 16384
#define DIM   1024
#define HID   2048
#define NEXP  8
#define TOPK  2
#define NSLOT (T_TOK*TOPK)                 // 32768
#define PADT  (NSLOT + NEXP*128)           // 33792 padded rows
#define ROWB  (PADT/128)                   // 264 row-blocks

// ---------------- device scratch (allocation-free rule) ----------------
__device__ int   g_counts[NEXP];
__device__ int   g_cntpad[NEXP];
__device__ int   g_offsets[NEXP];
__device__ int   g_perm[PADT];
__device__ int   g_rowOf[NSLOT];
__device__ int   g_sel[NSLOT];
__device__ float g_gwt[NSLOT];

// fp16 weight hi/lo splits; fp16 activations (single)
__device__ __half g_w1h[(size_t)NEXP*HID*DIM];
__device__ __half g_w1l[(size_t)NEXP*HID*DIM];
__device__ __half g_w3h[(size_t)NEXP*HID*DIM];
__device__ __half g_w3l[(size_t)NEXP*HID*DIM];
__device__ __half g_w2h[(size_t)NEXP*DIM*HID];
__device__ __half g_w2l[(size_t)NEXP*DIM*HID];
__device__ __half g_x [(size_t)PADT*DIM];
__device__ __half g_h [(size_t)PADT*HID];
__device__ float  g_y [(size_t)PADT*DIM];

// ---------------- helpers (base-PTX only) ----------------
__device__ __forceinline__ uint32_t smem_u32(const void* p) {
    uint32_t a;
    asm("{ .reg .u64 t; cvta.to.shared.u64 t, %1; cvt.u32.u64 %0, t; }" : "=r"(a) : "l"(p));
    return a;
}
__device__ __forceinline__ void cp16(uint32_t dst, const void* src) {
    asm volatile("cp.async.cg.shared.global [%0], [%1], 16;" :: "r"(dst), "l"(src));
}
__device__ __forceinline__ void cp_commit() {
    asm volatile("cp.async.commit_group;");
}
__device__ __forceinline__ void cp_wait0() {
    asm volatile("cp.async.wait_group 0;" ::: "memory");
}
// m16n8k16 row.col fp16 -> f32 accum (base PTX)
__device__ __forceinline__ void mma_f16(float c[4], const uint32_t a[4],
                                        uint32_t b0, uint32_t b1) {
    asm volatile(
        "mma.sync.aligned.m16n8k16.row.col.f32.f16.f16.f32 "
        "{%0,%1,%2,%3}, {%4,%5,%6,%7}, {%8,%9}, {%0,%1,%2,%3};"
        : "+f"(c[0]), "+f"(c[1]), "+f"(c[2]), "+f"(c[3])
        : "r"(a[0]), "r"(a[1]), "r"(a[2]), "r"(a[3]), "r"(b0), "r"(b1));
}
__device__ __forceinline__ void ldm_x4(uint32_t* r, uint32_t a) {
    asm volatile("ldmatrix.sync.aligned.m8n8.x4.shared.b16 {%0,%1,%2,%3}, [%4];"
                 : "=r"(r[0]), "=r"(r[1]), "=r"(r[2]), "=r"(r[3]) : "r"(a));
}
__device__ __forceinline__ int expert_of(int row0) {
    int e = 0;
#pragma unroll
    for (int i = 1; i < NEXP; i++) if (row0 >= g_offsets[i]) e = i;
    return e;
}

// ---------------- launch 0: gating (1 warp / token) ------
__global__ void gating_kernel(const float* __restrict__ x, const float* __restrict__ gw) {
    int t = (blockIdx.x * blockDim.x + threadIdx.x) >> 5;
    int lane = threadIdx.x & 31;
    if (t >= T_TOK) return;
    const float* xr = x + (size_t)t * DIM;
    float xv[DIM / 32];
#pragma unroll
    for (int i = 0; i < DIM / 32; i++) xv[i] = xr[lane + 32 * i];
    float logits[NEXP];
#pragma unroll
    for (int e = 0; e < NEXP; e++) {
        const float* g = gw + e * DIM;
        float acc = 0.f;
#pragma unroll
        for (int i = 0; i < DIM / 32; i++) acc = fmaf(xv[i], g[lane + 32 * i], acc);
#pragma unroll
        for (int o = 16; o; o >>= 1) acc += __shfl_xor_sync(0xffffffffu, acc, o);
        logits[e] = acc;
    }
    if (lane == 0) {
        int e0 = 0; float l0 = logits[0];
#pragma unroll
        for (int e = 1; e < NEXP; e++) if (logits[e] > l0) { l0 = logits[e]; e0 = e; }
        int e1 = (e0 == 0) ? 1 : 0; float l1 = logits[e1];
#pragma unroll
        for (int e = 0; e < NEXP; e++) if (e != e0 && logits[e] > l1) { l1 = logits[e]; e1 = e; }
        float p1 = __expf(l1 - l0);
        float inv = 1.f / (1.f + p1);
        g_sel[t * 2 + 0] = e0; g_sel[t * 2 + 1] = e1;
        g_gwt[t * 2 + 0] = inv; g_gwt[t * 2 + 1] = p1 * inv;
    }
}

// ---------------- launch 1: count + scan + scatter (single block) -----------
__global__ __launch_bounds__(1024) void scatscan_kernel() {
    __shared__ int scnt[NEXP];
    __shared__ int scur[NEXP];
    int tid = threadIdx.x;
    if (tid < NEXP) scnt[tid] = 0;
    __syncthreads();
    for (int idx = tid; idx < NSLOT; idx += 1024)
        atomicAdd(&scnt[g_sel[idx]], 1);
    __syncthreads();
    if (tid == 0) {
        int o = 0;
        for (int e = 0; e < NEXP; e++) {
            int c = scnt[e];
            int cp = (c + 127) & ~127;
            g_counts[e] = c;
            g_offsets[e] = o;
            g_cntpad[e] = cp;
            scur[e] = o;
            o += cp;
        }
    }
    __syncthreads();
    for (int idx = tid; idx < NSLOT; idx += 1024) {
        int e = g_sel[idx];
        int pos = atomicAdd(&scur[e], 1);
        g_perm[pos] = idx >> 1;
        g_rowOf[idx] = pos;
    }
}

// ---------------- launch 2: prep = gather(x->fp16) + weight hi/lo fp16 ------
#define WQ ((size_t)NEXP*HID*DIM/4)
#define WBLK ((unsigned)((3*WQ + 255) / 256))
__global__ __launch_bounds__(256) void prep_kernel(const float* __restrict__ x,
                                                   const float* __restrict__ w1,
                                                   const float* __restrict__ w3,
                                                   const float* __restrict__ w2) {
    int b = blockIdx.x;
    if (b < PADT) {
        int row = b;
        int e = -1, r = 0;
#pragma unroll
        for (int i = 0; i < NEXP; i++) {
            int o = g_offsets[i], c = g_cntpad[i];
            if (row >= o && row < o + c) { e = i; r = row - o; }
        }
        if (e < 0) return;
        float4 v = make_float4(0.f, 0.f, 0.f, 0.f);
        if (r < g_counts[e]) {
            int tok = g_perm[row];
            v = *(const float4*)(x + (size_t)tok * DIM + threadIdx.x * 4);
        }
        size_t o = (size_t)row * DIM + threadIdx.x * 4;
        __half2 a0, a1;
        a0.x = __float2half_rn(v.x); a0.y = __float2half_rn(v.y);
        a1.x = __float2half_rn(v.z); a1.y = __float2half_rn(v.w);
        ((__half2*)(g_x + o))[0] = a0;
        ((__half2*)(g_x + o))[1] = a1;
    } else {
        size_t i = (size_t)(b - PADT) * 256 + threadIdx.x;
        if (i >= 3 * WQ) return;
        const float* src; __half *hi, *lo; size_t j;
        if (i < WQ)          { src = w1; hi = g_w1h; lo = g_w1l; j = i; }
        else if (i < 2 * WQ) { src = w3; hi = g_w3h; lo = g_w3l; j = i - WQ; }
        else                 { src = w2; hi = g_w2h; lo = g_w2l; j = i - 2 * WQ; }
        float4 v = ((const float4*)src)[j];
        __half2 h0, h1, l0, l1;
        h0.x = __float2half_rn(v.x); h0.y = __float2half_rn(v.y);
        h1.x = __float2half_rn(v.z); h1.y = __float2half_rn(v.w);
        l0.x = __float2half_rn(v.x - __half2float(h0.x));
        l0.y = __float2half_rn(v.y - __half2float(h0.y));
        l1.x = __float2half_rn(v.z - __half2float(h1.x));
        l1.y = __float2half_rn(v.w - __half2float(h1.y));
        ((__half2*)(hi + 4 * j))[0] = h0;
        ((__half2*)(hi + 4 * j))[1] = h1;
        ((__half2*)(lo + 4 * j))[0] = l0;
        ((__half2*)(lo + 4 * j))[1] = l1;
    }
}

// ---------------- shared memory layouts (K-chunk = 64 halves = 128 B) -------
#define SAW 144    // 128B data + 16B pad per row: 16B aligned, conflict-free
// GEMM1: A [128x64], B1/B3 hi/lo [64x64]
#define G1_A   0
#define G1_B1H 18432
#define G1_B1L 27648
#define G1_B3H 36864
#define G1_B3L 46080
#define G1_STAGE 55296
#define G1_SMEM (2*G1_STAGE)    // 110592/CTA, 2 CTAs = 216 KB
// GEMM2: A [128x64], B hi/lo [64x64]
#define G2_A   0
#define G2_BH  18432
#define G2_BL  27648
#define G2_STAGE 36864
#define G2_SMEM (2*G2_STAGE)

// ---------------- GEMM1: hidden = silu(x@w1^T) * (x@w3^T), fp16 2-pass ------
__device__ __forceinline__ void g1_load(uint32_t st,
        const __half* A,
        const __half* B1h, const __half* B1l,
        const __half* B3h, const __half* B3l, int kt, int tid) {
    // A: 128 rows x 128B = 1024 chunks -> 4/thread
#pragma unroll
    for (int i = 0; i < 4; i++) {
        int idx = tid + i * 256;
        int m = idx >> 3, c = idx & 7;
        cp16(st + G1_A + m * SAW + c * 16, A + (size_t)m * DIM + kt + c * 8);
    }
    // each B tile: 64 rows x 128B = 512 chunks -> 2/thread
#pragma unroll
    for (int i = 0; i < 2; i++) {
        int idx = tid + i * 256;
        int n = idx >> 3, c = idx & 7;
        cp16(st + G1_B1H + n * SAW + c * 16, B1h + (size_t)n * DIM + kt + c * 8);
        cp16(st + G1_B1L + n * SAW + c * 16, B1l + (size_t)n * DIM + kt + c * 8);
        cp16(st + G1_B3H + n * SAW + c * 16, B3h + (size_t)n * DIM + kt + c * 8);
        cp16(st + G1_B3L + n * SAW + c * 16, B3l + (size_t)n * DIM + kt + c * 8);
    }
}

__global__ __launch_bounds__(256, 2) void gemm1_mma() {
    int row0 = blockIdx.y * 128;
    if (row0 >= g_offsets[NEXP - 1] + g_cntpad[NEXP - 1]) return;
    int e = expert_of(row0);
    int n0 = blockIdx.x * 64;

    extern __shared__ __align__(16) char smem[];
    uint32_t sb = smem_u32(smem);
    int tid = threadIdx.x, lane = tid & 31, warp = tid >> 5;
    int gr = lane >> 2, gc2 = (lane & 3) * 2;
    int wm = (warp & 3) * 32;
    int wn = (warp >> 2) * 32;

    const __half* A   = g_x + (size_t)row0 * DIM;
    const size_t wb = ((size_t)e * HID + n0) * DIM;
    const __half* B1h = g_w1h + wb;
    const __half* B1l = g_w1l + wb;
    const __half* B3h = g_w3h + wb;
    const __half* B3l = g_w3l + wb;

    float acc1[2][4][4], acc3[2][4][4];
#pragma unroll
    for (int i = 0; i < 2; i++)
#pragma unroll
        for (int j = 0; j < 4; j++)
#pragma unroll
            for (int q = 0; q < 4; q++) { acc1[i][j][q] = 0.f; acc3[i][j][q] = 0.f; }

    uint32_t aAddr = (lane & 15) * SAW + (lane >> 4) * 16;
    uint32_t bAddr = (((lane >> 4) & 1) * 8 + (lane & 7)) * SAW + ((lane >> 3) & 1) * 16;

    const int NK = DIM / 64;   // 16
    g1_load(sb, A, B1h, B1l, B3h, B3l, 0, tid);
    cp_commit();

#pragma unroll 1
    for (int kc = 0; kc < NK; kc++) {
        cp_wait0();
        __syncthreads();
        if (kc + 1 < NK) {
            g1_load(sb + ((kc + 1) & 1) * G1_STAGE, A, B1h, B1l, B3h, B3l,
                    (kc + 1) * 64, tid);
            cp_commit();
        }
        uint32_t stv = sb + (kc & 1) * G1_STAGE;
#pragma unroll
        for (int ks = 0; ks < 4; ks++) {
            uint32_t k0b = ks * 32;
            uint32_t a[2][4];
#pragma unroll
            for (int i = 0; i < 2; i++)
                ldm_x4(a[i], stv + G1_A + (wm + i * 16) * SAW + aAddr + k0b);
#pragma unroll
            for (int jp = 0; jp < 2; jp++) {
                uint32_t rb = (wn + jp * 16) * SAW + bAddr + k0b;
                int j0 = jp * 2, j1 = jp * 2 + 1;
                uint32_t bh[4], bl[4];
                ldm_x4(bh, stv + G1_B1H + rb);
                ldm_x4(bl, stv + G1_B1L + rb);
#pragma unroll
                for (int i = 0; i < 2; i++) {
                    mma_f16(acc1[i][j0], a[i], bh[0], bh[1]);
                    mma_f16(acc1[i][j1], a[i], bh[2], bh[3]);
                    mma_f16(acc1[i][j0], a[i], bl[0], bl[1]);
                    mma_f16(acc1[i][j1], a[i], bl[2], bl[3]);
                }
                ldm_x4(bh, stv + G1_B3H + rb);
                ldm_x4(bl, stv + G1_B3L + rb);
#pragma unroll
                for (int i = 0; i < 2; i++) {
                    mma_f16(acc3[i][j0], a[i], bh[0], bh[1]);
                    mma_f16(acc3[i][j1], a[i], bh[2], bh[3]);
                    mma_f16(acc3[i][j0], a[i], bl[0], bl[1]);
                    mma_f16(acc3[i][j1], a[i], bl[2], bl[3]);
                }
            }
        }
    }

    // epilogue: silu(h1)*h3 -> fp16 hidden
#pragma unroll
    for (int i = 0; i < 2; i++)
#pragma unroll
        for (int j = 0; j < 4; j++) {
            int m = wm + i * 16 + gr;
            int n = wn + j * 8 + gc2;
#pragma unroll
            for (int half = 0; half < 2; half++) {
                int mm = m + half * 8;
                float h1a = acc1[i][j][half * 2 + 0], h1b = acc1[i][j][half * 2 + 1];
                float h3a = acc3[i][j][half * 2 + 0], h3b = acc3[i][j][half * 2 + 1];
                float v0 = h3a * h1a / (1.f + __expf(-h1a));
                float v1 = h3b * h1b / (1.f + __expf(-h1b));
                __half2 hv;
                hv.x = __float2half_rn(v0);
                hv.y = __float2half_rn(v1);
                *(__half2*)(g_h + (size_t)(row0 + mm) * HID + n0 + n) = hv;
            }
        }
}

// ---------------- GEMM2: y = hidden @ w2^T, fp16 2-pass, tile 128x64 --------
__device__ __forceinline__ void g2_load(uint32_t st,
        const __half* A, const __half* Bh, const __half* Bl, int kt, int tid) {
#pragma unroll
    for (int i = 0; i < 4; i++) {
        int idx = tid + i * 256;
        int m = idx >> 3, c = idx & 7;
        cp16(st + G2_A + m * SAW + c * 16, A + (size_t)m * HID + kt + c * 8);
    }
#pragma unroll
    for (int i = 0; i < 2; i++) {
        int idx = tid + i * 256;
        int n = idx >> 3, c = idx & 7;
        cp16(st + G2_BH + n * SAW + c * 16, Bh + (size_t)n * HID + kt + c * 8);
        cp16(st + G2_BL + n * SAW + c * 16, Bl + (size_t)n * HID + kt + c * 8);
    }
}

__global__ __launch_bounds__(256, 2) void gemm2_mma() {
    int row0 = blockIdx.y * 128;
    if (row0 >= g_offsets[NEXP - 1] + g_cntpad[NEXP - 1]) return;
    int e = expert_of(row0);
    int n0 = blockIdx.x * 64;

    extern __shared__ __align__(16) char smem[];
    uint32_t sb = smem_u32(smem);
    int tid = threadIdx.x, lane = tid & 31, warp = tid >> 5;
    int gr = lane >> 2, gc2 = (lane & 3) * 2;
    int wm = (warp & 3) * 32;
    int wn = (warp >> 2) * 32;

    const __half* A  = g_h + (size_t)row0 * HID;
    const size_t wb = ((size_t)e * DIM + n0) * HID;
    const __half* Bh = g_w2h + wb;
    const __half* Bl = g_w2l + wb;

    float acc[2][4][4];
#pragma unroll
    for (int i = 0; i < 2; i++)
#pragma unroll
        for (int j = 0; j < 4; j++)
#pragma unroll
            for (int q = 0; q < 4; q++) acc[i][j][q] = 0.f;

    uint32_t aAddr = (lane & 15) * SAW + (lane >> 4) * 16;
    uint32_t bAddr = (((lane >> 4) & 1) * 8 + (lane & 7)) * SAW + ((lane >> 3) & 1) * 16;

    const int NK = HID / 64;   // 32
    g2_load(sb, A, Bh, Bl, 0, tid);
    cp_commit();

#pragma unroll 1
    for (int kc = 0; kc < NK; kc++) {
        cp_wait0();
        __syncthreads();
        if (kc + 1 < NK) {
            g2_load(sb + ((kc + 1) & 1) * G2_STAGE, A, Bh, Bl, (kc + 1) * 64, tid);
            cp_commit();
        }
        uint32_t stv = sb + (kc & 1) * G2_STAGE;
#pragma unroll
        for (int ks = 0; ks < 4; ks++) {
            uint32_t k0b = ks * 32;
            uint32_t a[2][4];
#pragma unroll
            for (int i = 0; i < 2; i++)
                ldm_x4(a[i], stv + G2_A + (wm + i * 16) * SAW + aAddr + k0b);
#pragma unroll
            for (int jp = 0; jp < 2; jp++) {
                uint32_t rb = (wn + jp * 16) * SAW + bAddr + k0b;
                int j0 = jp * 2, j1 = jp * 2 + 1;
                uint32_t bh[4], bl[4];
                ldm_x4(bh, stv + G2_BH + rb);
                ldm_x4(bl, stv + G2_BL + rb);
#pragma unroll
                for (int i = 0; i < 2; i++) {
                    mma_f16(acc[i][j0], a[i], bh[0], bh[1]);
                    mma_f16(acc[i][j1], a[i], bh[2], bh[3]);
                    mma_f16(acc[i][j0], a[i], bl[0], bl[1]);
                    mma_f16(acc[i][j1], a[i], bl[2], bl[3]);
                }
            }
        }
    }

#pragma unroll
    for (int i = 0; i < 2; i++)
#pragma unroll
        for (int j = 0; j < 4; j++) {
            int m = wm + i * 16 + gr;
            int n = wn + j * 8 + gc2;
#pragma unroll
            for (int half = 0; half < 2; half++) {
                int mm = m + half * 8;
                float2 v = make_float2(acc[i][j][half * 2 + 0], acc[i][j][half * 2 + 1]);
                *(float2*)(g_y + (size_t)(row0 + mm) * DIM + n0 + n) = v;
            }
        }
}

// ---------------- launch 5: combine ----------------
__global__ void combine_kernel(float* __restrict__ out) {
    int idx = blockIdx.x * blockDim.x + threadIdx.x;
    if (idx >= T_TOK * DIM / 4) return;
    int t = idx / (DIM / 4);
    int d4 = idx - t * (DIM / 4);
    float w0 = g_gwt[t * 2 + 0], w1 = g_gwt[t * 2 + 1];
    const float4 y0 = *(const float4*)(g_y + (size_t)g_rowOf[t * 2 + 0] * DIM + d4 * 4);
    const float4 y1 = *(const float4*)(g_y + (size_t)g_rowOf[t * 2 + 1] * DIM + d4 * 4);
    float4 o;
    o.x = w0 * y0.x + w1 * y1.x;
    o.y = w0 * y0.y + w1 * y1.y;
    o.z = w0 * y0.z + w1 * y1.z;
    o.w = w0 * y0.w + w1 * y1.w;
    ((float4*)out)[idx] = o;
}

// ---------------- launch ----------------
extern "C" void kernel_launch(void* const* d_in, const int* in_sizes, int n_in,
                              void* d_out, int out_size) {
    const float* x  = (const float*)d_in[0];
    const float* gw = (const float*)d_in[1];
    const float* w1 = (const float*)d_in[2];
    const float* w3 = (const float*)d_in[3];
    const float* w2 = (const float*)d_in[4];
    float* out = (float*)d_out;

    cudaFuncSetAttribute(gemm1_mma, cudaFuncAttributeMaxDynamicSharedMemorySize, G1_SMEM);
    cudaFuncSetAttribute(gemm2_mma, cudaFuncAttributeMaxDynamicSharedMemorySize, G2_SMEM);

    gating_kernel<<<T_TOK / 8, 256>>>(x, gw);                          // 0
    scatscan_kernel<<<1, 1024>>>();                                    // 1
    prep_kernel<<<PADT + WBLK, 256>>>(x, w1, w3, w2);                  // 2
    gemm1_mma<<<dim3(HID / 64, ROWB), 256, G1_SMEM>>>();               // 3 (ncu -s 5 target)
    gemm2_mma<<<dim3(DIM / 64, ROWB), 256, G2_SMEM>>>();               // 4
    combine_kernel<<<(T_TOK * DIM / 4 + 255) / 256, 256>>>(out);       // 5
}

// round 14
// speedup vs baseline: 1.9530x; 1.1451x over previous
#include <cuda_runtime.h>
#include <cuda_fp16.h>
#include <math.h>
#include <stdint.h>

// ---------------- problem constants ----------------
#define T_TOK 16384
#define DIM   1024
#define HID   2048
#define NEXP  8
#define TOPK  2
#define NSLOT (T_TOK*TOPK)                 // 32768
#define PADT  (NSLOT + NEXP*128)           // 33792 padded rows
#define ROWB  (PADT/128)                   // 264 row-blocks

// ---------------- device scratch (allocation-free rule) ----------------
__device__ int   g_counts[NEXP];
__device__ int   g_cntpad[NEXP];
__device__ int   g_offsets[NEXP];
__device__ int   g_perm[PADT];
__device__ int   g_rowOf[NSLOT];
__device__ int   g_sel[NSLOT];
__device__ float g_gwt[NSLOT];

// fp16 weight splits (w1/w3 hi+lo, w2 hi only); fp16 activations
__device__ __half g_w1h[(size_t)NEXP*HID*DIM];
__device__ __half g_w1l[(size_t)NEXP*HID*DIM];
__device__ __half g_w3h[(size_t)NEXP*HID*DIM];
__device__ __half g_w3l[(size_t)NEXP*HID*DIM];
__device__ __half g_w2h[(size_t)NEXP*DIM*HID];
__device__ __half g_x [(size_t)PADT*DIM];
__device__ __half g_h [(size_t)PADT*HID];
__device__ float  g_y [(size_t)PADT*DIM];

// ---------------- helpers (base-PTX only) ----------------
__device__ __forceinline__ uint32_t smem_u32(const void* p) {
    uint32_t a;
    asm("{ .reg .u64 t; cvta.to.shared.u64 t, %1; cvt.u32.u64 %0, t; }" : "=r"(a) : "l"(p));
    return a;
}
__device__ __forceinline__ void cp16(uint32_t dst, const void* src) {
    asm volatile("cp.async.cg.shared.global [%0], [%1], 16;" :: "r"(dst), "l"(src));
}
__device__ __forceinline__ void cp_commit() {
    asm volatile("cp.async.commit_group;");
}
__device__ __forceinline__ void cp_wait0() {
    asm volatile("cp.async.wait_group 0;" ::: "memory");
}
// m16n8k16 row.col fp16 -> f32 accum (base PTX)
__device__ __forceinline__ void mma_f16(float c[4], const uint32_t a[4],
                                        uint32_t b0, uint32_t b1) {
    asm volatile(
        "mma.sync.aligned.m16n8k16.row.col.f32.f16.f16.f32 "
        "{%0,%1,%2,%3}, {%4,%5,%6,%7}, {%8,%9}, {%0,%1,%2,%3};"
        : "+f"(c[0]), "+f"(c[1]), "+f"(c[2]), "+f"(c[3])
        : "r"(a[0]), "r"(a[1]), "r"(a[2]), "r"(a[3]), "r"(b0), "r"(b1));
}
__device__ __forceinline__ void ldm_x4(uint32_t* r, uint32_t a) {
    asm volatile("ldmatrix.sync.aligned.m8n8.x4.shared.b16 {%0,%1,%2,%3}, [%4];"
                 : "=r"(r[0]), "=r"(r[1]), "=r"(r[2]), "=r"(r[3]) : "r"(a));
}
__device__ __forceinline__ int expert_of(int row0) {
    int e = 0;
#pragma unroll
    for (int i = 1; i < NEXP; i++) if (row0 >= g_offsets[i]) e = i;
    return e;
}

// ---------------- launch 0: gating (1 warp / token) ------
__global__ void gating_kernel(const float* __restrict__ x, const float* __restrict__ gw) {
    int t = (blockIdx.x * blockDim.x + threadIdx.x) >> 5;
    int lane = threadIdx.x & 31;
    if (t >= T_TOK) return;
    const float* xr = x + (size_t)t * DIM;
    float xv[DIM / 32];
#pragma unroll
    for (int i = 0; i < DIM / 32; i++) xv[i] = xr[lane + 32 * i];
    float logits[NEXP];
#pragma unroll
    for (int e = 0; e < NEXP; e++) {
        const float* g = gw + e * DIM;
        float acc = 0.f;
#pragma unroll
        for (int i = 0; i < DIM / 32; i++) acc = fmaf(xv[i], g[lane + 32 * i], acc);
#pragma unroll
        for (int o = 16; o; o >>= 1) acc += __shfl_xor_sync(0xffffffffu, acc, o);
        logits[e] = acc;
    }
    if (lane == 0) {
        int e0 = 0; float l0 = logits[0];
#pragma unroll
        for (int e = 1; e < NEXP; e++) if (logits[e] > l0) { l0 = logits[e]; e0 = e; }
        int e1 = (e0 == 0) ? 1 : 0; float l1 = logits[e1];
#pragma unroll
        for (int e = 0; e < NEXP; e++) if (e != e0 && logits[e] > l1) { l1 = logits[e]; e1 = e; }
        float p1 = __expf(l1 - l0);
        float inv = 1.f / (1.f + p1);
        g_sel[t * 2 + 0] = e0; g_sel[t * 2 + 1] = e1;
        g_gwt[t * 2 + 0] = inv; g_gwt[t * 2 + 1] = p1 * inv;
    }
}

// ---------------- launch 1: count + scan + scatter (single block) -----------
__global__ __launch_bounds__(1024) void scatscan_kernel() {
    __shared__ int scnt[NEXP];
    __shared__ int scur[NEXP];
    int tid = threadIdx.x;
    if (tid < NEXP) scnt[tid] = 0;
    __syncthreads();
    for (int idx = tid; idx < NSLOT; idx += 1024)
        atomicAdd(&scnt[g_sel[idx]], 1);
    __syncthreads();
    if (tid == 0) {
        int o = 0;
        for (int e = 0; e < NEXP; e++) {
            int c = scnt[e];
            int cp = (c + 127) & ~127;
            g_counts[e] = c;
            g_offsets[e] = o;
            g_cntpad[e] = cp;
            scur[e] = o;
            o += cp;
        }
    }
    __syncthreads();
    for (int idx = tid; idx < NSLOT; idx += 1024) {
        int e = g_sel[idx];
        int pos = atomicAdd(&scur[e], 1);
        g_perm[pos] = idx >> 1;
        g_rowOf[idx] = pos;
    }
}

// ---------------- launch 2: prep = gather(x->fp16) + weight convert ---------
#define WQ ((size_t)NEXP*HID*DIM/4)
#define WBLK ((unsigned)((3*WQ + 255) / 256))
__global__ __launch_bounds__(256) void prep_kernel(const float* __restrict__ x,
                                                   const float* __restrict__ w1,
                                                   const float* __restrict__ w3,
                                                   const float* __restrict__ w2) {
    int b = blockIdx.x;
    if (b < PADT) {
        int row = b;
        int e = -1, r = 0;
#pragma unroll
        for (int i = 0; i < NEXP; i++) {
            int o = g_offsets[i], c = g_cntpad[i];
            if (row >= o && row < o + c) { e = i; r = row - o; }
        }
        if (e < 0) return;
        float4 v = make_float4(0.f, 0.f, 0.f, 0.f);
        if (r < g_counts[e]) {
            int tok = g_perm[row];
            v = *(const float4*)(x + (size_t)tok * DIM + threadIdx.x * 4);
        }
        size_t o = (size_t)row * DIM + threadIdx.x * 4;
        __half2 a0, a1;
        a0.x = __float2half_rn(v.x); a0.y = __float2half_rn(v.y);
        a1.x = __float2half_rn(v.z); a1.y = __float2half_rn(v.w);
        ((__half2*)(g_x + o))[0] = a0;
        ((__half2*)(g_x + o))[1] = a1;
    } else {
        size_t i = (size_t)(b - PADT) * 256 + threadIdx.x;
        if (i >= 3 * WQ) return;
        if (i >= 2 * WQ) {
            // w2: hi only
            size_t j = i - 2 * WQ;
            float4 v = ((const float4*)w2)[j];
            __half2 h0, h1;
            h0.x = __float2half_rn(v.x); h0.y = __float2half_rn(v.y);
            h1.x = __float2half_rn(v.z); h1.y = __float2half_rn(v.w);
            ((__half2*)(g_w2h + 4 * j))[0] = h0;
            ((__half2*)(g_w2h + 4 * j))[1] = h1;
            return;
        }
        const float* src; __half *hi, *lo; size_t j;
        if (i < WQ) { src = w1; hi = g_w1h; lo = g_w1l; j = i; }
        else        { src = w3; hi = g_w3h; lo = g_w3l; j = i - WQ; }
        float4 v = ((const float4*)src)[j];
        __half2 h0, h1, l0, l1;
        h0.x = __float2half_rn(v.x); h0.y = __float2half_rn(v.y);
        h1.x = __float2half_rn(v.z); h1.y = __float2half_rn(v.w);
        l0.x = __float2half_rn(v.x - __half2float(h0.x));
        l0.y = __float2half_rn(v.y - __half2float(h0.y));
        l1.x = __float2half_rn(v.z - __half2float(h1.x));
        l1.y = __float2half_rn(v.w - __half2float(h1.y));
        ((__half2*)(hi + 4 * j))[0] = h0;
        ((__half2*)(hi + 4 * j))[1] = h1;
        ((__half2*)(lo + 4 * j))[0] = l0;
        ((__half2*)(lo + 4 * j))[1] = l1;
    }
}

// ---------------- shared memory layouts ----------------
// GEMM1: K-chunk 64 (128B rows + 16B pad)
#define SAW 144
#define G1_A   0
#define G1_B1H 18432
#define G1_B1L 27648
#define G1_B3H 36864
#define G1_B3L 46080
#define G1_STAGE 55296
#define G1_SMEM (2*G1_STAGE)    // 110592/CTA, 2 CTAs = 216 KB
// GEMM2: K-chunk 128 (256B rows + 16B pad), 1-pass (Bh only)
#define SAW2 272
#define G2_A   0
#define G2_BH  34816            // 128*272
#define G2_STAGE 52224          // + 64*272
#define G2_SMEM (2*G2_STAGE)    // 104448/CTA, 2 CTAs = 204 KB

// ---------------- GEMM1: hidden = silu(x@w1^T) * (x@w3^T), fp16 2-pass ------
__device__ __forceinline__ void g1_load(uint32_t st,
        const __half* A,
        const __half* B1h, const __half* B1l,
        const __half* B3h, const __half* B3l, int kt, int tid) {
#pragma unroll
    for (int i = 0; i < 4; i++) {
        int idx = tid + i * 256;
        int m = idx >> 3, c = idx & 7;
        cp16(st + G1_A + m * SAW + c * 16, A + (size_t)m * DIM + kt + c * 8);
    }
#pragma unroll
    for (int i = 0; i < 2; i++) {
        int idx = tid + i * 256;
        int n = idx >> 3, c = idx & 7;
        cp16(st + G1_B1H + n * SAW + c * 16, B1h + (size_t)n * DIM + kt + c * 8);
        cp16(st + G1_B1L + n * SAW + c * 16, B1l + (size_t)n * DIM + kt + c * 8);
        cp16(st + G1_B3H + n * SAW + c * 16, B3h + (size_t)n * DIM + kt + c * 8);
        cp16(st + G1_B3L + n * SAW + c * 16, B3l + (size_t)n * DIM + kt + c * 8);
    }
}

__global__ __launch_bounds__(256, 2) void gemm1_mma() {
    int row0 = blockIdx.y * 128;
    if (row0 >= g_offsets[NEXP - 1] + g_cntpad[NEXP - 1]) return;
    int e = expert_of(row0);
    int n0 = blockIdx.x * 64;

    extern __shared__ __align__(16) char smem[];
    uint32_t sb = smem_u32(smem);
    int tid = threadIdx.x, lane = tid & 31, warp = tid >> 5;
    int gr = lane >> 2, gc2 = (lane & 3) * 2;
    int wm = (warp & 3) * 32;
    int wn = (warp >> 2) * 32;

    const __half* A   = g_x + (size_t)row0 * DIM;
    const size_t wb = ((size_t)e * HID + n0) * DIM;
    const __half* B1h = g_w1h + wb;
    const __half* B1l = g_w1l + wb;
    const __half* B3h = g_w3h + wb;
    const __half* B3l = g_w3l + wb;

    float acc1[2][4][4], acc3[2][4][4];
#pragma unroll
    for (int i = 0; i < 2; i++)
#pragma unroll
        for (int j = 0; j < 4; j++)
#pragma unroll
            for (int q = 0; q < 4; q++) { acc1[i][j][q] = 0.f; acc3[i][j][q] = 0.f; }

    uint32_t aAddr = (lane & 15) * SAW + (lane >> 4) * 16;
    uint32_t bAddr = (((lane >> 4) & 1) * 8 + (lane & 7)) * SAW + ((lane >> 3) & 1) * 16;

    const int NK = DIM / 64;   // 16
    g1_load(sb, A, B1h, B1l, B3h, B3l, 0, tid);
    cp_commit();

#pragma unroll 1
    for (int kc = 0; kc < NK; kc++) {
        cp_wait0();
        __syncthreads();
        if (kc + 1 < NK) {
            g1_load(sb + ((kc + 1) & 1) * G1_STAGE, A, B1h, B1l, B3h, B3l,
                    (kc + 1) * 64, tid);
            cp_commit();
        }
        uint32_t stv = sb + (kc & 1) * G1_STAGE;
#pragma unroll
        for (int ks = 0; ks < 4; ks++) {
            uint32_t k0b = ks * 32;
            uint32_t a[2][4];
#pragma unroll
            for (int i = 0; i < 2; i++)
                ldm_x4(a[i], stv + G1_A + (wm + i * 16) * SAW + aAddr + k0b);
#pragma unroll
            for (int jp = 0; jp < 2; jp++) {
                uint32_t rb = (wn + jp * 16) * SAW + bAddr + k0b;
                int j0 = jp * 2, j1 = jp * 2 + 1;
                uint32_t bh[4], bl[4];
                ldm_x4(bh, stv + G1_B1H + rb);
                ldm_x4(bl, stv + G1_B1L + rb);
#pragma unroll
                for (int i = 0; i < 2; i++) {
                    mma_f16(acc1[i][j0], a[i], bh[0], bh[1]);
                    mma_f16(acc1[i][j1], a[i], bh[2], bh[3]);
                    mma_f16(acc1[i][j0], a[i], bl[0], bl[1]);
                    mma_f16(acc1[i][j1], a[i], bl[2], bl[3]);
                }
                ldm_x4(bh, stv + G1_B3H + rb);
                ldm_x4(bl, stv + G1_B3L + rb);
#pragma unroll
                for (int i = 0; i < 2; i++) {
                    mma_f16(acc3[i][j0], a[i], bh[0], bh[1]);
                    mma_f16(acc3[i][j1], a[i], bh[2], bh[3]);
                    mma_f16(acc3[i][j0], a[i], bl[0], bl[1]);
                    mma_f16(acc3[i][j1], a[i], bl[2], bl[3]);
                }
            }
        }
    }

    // epilogue: silu(h1)*h3 -> fp16 hidden
#pragma unroll
    for (int i = 0; i < 2; i++)
#pragma unroll
        for (int j = 0; j < 4; j++) {
            int m = wm + i * 16 + gr;
            int n = wn + j * 8 + gc2;
#pragma unroll
            for (int half = 0; half < 2; half++) {
                int mm = m + half * 8;
                float h1a = acc1[i][j][half * 2 + 0], h1b = acc1[i][j][half * 2 + 1];
                float h3a = acc3[i][j][half * 2 + 0], h3b = acc3[i][j][half * 2 + 1];
                float v0 = h3a * h1a / (1.f + __expf(-h1a));
                float v1 = h3b * h1b / (1.f + __expf(-h1b));
                __half2 hv;
                hv.x = __float2half_rn(v0);
                hv.y = __float2half_rn(v1);
                *(__half2*)(g_h + (size_t)(row0 + mm) * HID + n0 + n) = hv;
            }
        }
}

// ---------------- GEMM2: y = hidden @ w2h^T, fp16 1-pass, K-chunk 128 -------
__device__ __forceinline__ void g2_load(uint32_t st,
        const __half* A, const __half* Bh, int kt, int tid) {
    // A: 128 rows x 256B = 2048 chunks -> 8/thread
#pragma unroll
    for (int i = 0; i < 8; i++) {
        int idx = tid + i * 256;
        int m = idx >> 4, c = idx & 15;
        cp16(st + G2_A + m * SAW2 + c * 16, A + (size_t)m * HID + kt + c * 8);
    }
    // B: 64 rows x 256B = 1024 chunks -> 4/thread
#pragma unroll
    for (int i = 0; i < 4; i++) {
        int idx = tid + i * 256;
        int n = idx >> 4, c = idx & 15;
        cp16(st + G2_BH + n * SAW2 + c * 16, Bh + (size_t)n * HID + kt + c * 8);
    }
}

__global__ __launch_bounds__(256, 2) void gemm2_mma() {
    int row0 = blockIdx.y * 128;
    if (row0 >= g_offsets[NEXP - 1] + g_cntpad[NEXP - 1]) return;
    int e = expert_of(row0);
    int n0 = blockIdx.x * 64;

    extern __shared__ __align__(16) char smem[];
    uint32_t sb = smem_u32(smem);
    int tid = threadIdx.x, lane = tid & 31, warp = tid >> 5;
    int gr = lane >> 2, gc2 = (lane & 3) * 2;
    int wm = (warp & 3) * 32;
    int wn = (warp >> 2) * 32;

    const __half* A  = g_h + (size_t)row0 * HID;
    const __half* Bh = g_w2h + ((size_t)e * DIM + n0) * HID;

    float acc[2][4][4];
#pragma unroll
    for (int i = 0; i < 2; i++)
#pragma unroll
        for (int j = 0; j < 4; j++)
#pragma unroll
            for (int q = 0; q < 4; q++) acc[i][j][q] = 0.f;

    uint32_t aAddr = (lane & 15) * SAW2 + (lane >> 4) * 16;
    uint32_t bAddr = (((lane >> 4) & 1) * 8 + (lane & 7)) * SAW2 + ((lane >> 3) & 1) * 16;

    const int NK = HID / 128;   // 16
    g2_load(sb, A, Bh, 0, tid);
    cp_commit();

#pragma unroll 1
    for (int kc = 0; kc < NK; kc++) {
        cp_wait0();
        __syncthreads();
        if (kc + 1 < NK) {
            g2_load(sb + ((kc + 1) & 1) * G2_STAGE, A, Bh, (kc + 1) * 128, tid);
            cp_commit();
        }
        uint32_t stv = sb + (kc & 1) * G2_STAGE;
#pragma unroll
        for (int ks = 0; ks < 8; ks++) {
            uint32_t k0b = ks * 32;
            uint32_t a[2][4];
#pragma unroll
            for (int i = 0; i < 2; i++)
                ldm_x4(a[i], stv + G2_A + (wm + i * 16) * SAW2 + aAddr + k0b);
#pragma unroll
            for (int jp = 0; jp < 2; jp++) {
                uint32_t rb = (wn + jp * 16) * SAW2 + bAddr + k0b;
                int j0 = jp * 2, j1 = jp * 2 + 1;
                uint32_t bh[4];
                ldm_x4(bh, stv + G2_BH + rb);
#pragma unroll
                for (int i = 0; i < 2; i++) {
                    mma_f16(acc[i][j0], a[i], bh[0], bh[1]);
                    mma_f16(acc[i][j1], a[i], bh[2], bh[3]);
                }
            }
        }
    }

#pragma unroll
    for (int i = 0; i < 2; i++)
#pragma unroll
        for (int j = 0; j < 4; j++) {
            int m = wm + i * 16 + gr;
            int n = wn + j * 8 + gc2;
#pragma unroll
            for (int half = 0; half < 2; half++) {
                int mm = m + half * 8;
                float2 v = make_float2(acc[i][j][half * 2 + 0], acc[i][j][half * 2 + 1]);
                *(float2*)(g_y + (size_t)(row0 + mm) * DIM + n0 + n) = v;
            }
        }
}

// ---------------- launch 5: combine ----------------
__global__ void combine_kernel(float* __restrict__ out) {
    int idx = blockIdx.x * blockDim.x + threadIdx.x;
    if (idx >= T_TOK * DIM / 4) return;
    int t = idx / (DIM / 4);
    int d4 = idx - t * (DIM / 4);
    float w0 = g_gwt[t * 2 + 0], w1 = g_gwt[t * 2 + 1];
    const float4 y0 = *(const float4*)(g_y + (size_t)g_rowOf[t * 2 + 0] * DIM + d4 * 4);
    const float4 y1 = *(const float4*)(g_y + (size_t)g_rowOf[t * 2 + 1] * DIM + d4 * 4);
    float4 o;
    o.x = w0 * y0.x + w1 * y1.x;
    o.y = w0 * y0.y + w1 * y1.y;
    o.z = w0 * y0.z + w1 * y1.z;
    o.w = w0 * y0.w + w1 * y1.w;
    ((float4*)out)[idx] = o;
}

// ---------------- launch ----------------
extern "C" void kernel_launch(void* const* d_in, const int* in_sizes, int n_in,
                              void* d_out, int out_size) {
    const float* x  = (const float*)d_in[0];
    const float* gw = (const float*)d_in[1];
    const float* w1 = (const float*)d_in[2];
    const float* w3 = (const float*)d_in[3];
    const float* w2 = (const float*)d_in[4];
    float* out = (float*)d_out;

    cudaFuncSetAttribute(gemm1_mma, cudaFuncAttributeMaxDynamicSharedMemorySize, G1_SMEM);
    cudaFuncSetAttribute(gemm2_mma, cudaFuncAttributeMaxDynamicSharedMemorySize, G2_SMEM);

    gating_kernel<<<T_TOK / 8, 256>>>(x, gw);                          // 0
    scatscan_kernel<<<1, 1024>>>();                                    // 1
    prep_kernel<<<PADT + WBLK, 256>>>(x, w1, w3, w2);                  // 2
    gemm1_mma<<<dim3(HID / 64, ROWB), 256, G1_SMEM>>>();               // 3 (ncu -s 5 target)
    gemm2_mma<<<dim3(DIM / 64, ROWB), 256, G2_SMEM>>>();               // 4
    combine_kernel<<<(T_TOK * DIM / 4 + 255) / 256, 256>>>(out);       // 5
}

// round 15
// speedup vs baseline: 2.7812x; 1.4240x over previous
#include <cuda_runtime.h>
#include <cuda_fp16.h>
#include <math.h>
#include <stdint.h>

// ---------------- problem constants ----------------
#define T_TOK 16384
#define DIM   1024
#define HID   2048
#define NEXP  8
#define TOPK  2
#define NSLOT (T_TOK*TOPK)                 // 32768
#define PADT  (NSLOT + NEXP*128)           // 33792 padded rows
#define ROWB  (PADT/128)                   // 264 row-blocks

// ---------------- device scratch (allocation-free rule) ----------------
__device__ int   g_counts[NEXP];
__device__ int   g_cntpad[NEXP];
__device__ int   g_offsets[NEXP];
__device__ int   g_perm[PADT];
__device__ int   g_rowOf[NSLOT];
__device__ int   g_sel[NSLOT];
__device__ float g_gwt[NSLOT];

// fp16 weights (hi only — full 1-pass); fp16 activations
__device__ __half g_w1h[(size_t)NEXP*HID*DIM];
__device__ __half g_w3h[(size_t)NEXP*HID*DIM];
__device__ __half g_w2h[(size_t)NEXP*DIM*HID];
__device__ __half g_x [(size_t)PADT*DIM];
__device__ __half g_h [(size_t)PADT*HID];
__device__ float  g_y [(size_t)PADT*DIM];

// ---------------- helpers (base-PTX only) ----------------
__device__ __forceinline__ uint32_t smem_u32(const void* p) {
    uint32_t a;
    asm("{ .reg .u64 t; cvta.to.shared.u64 t, %1; cvt.u32.u64 %0, t; }" : "=r"(a) : "l"(p));
    return a;
}
__device__ __forceinline__ void cp16(uint32_t dst, const void* src) {
    asm volatile("cp.async.cg.shared.global [%0], [%1], 16;" :: "r"(dst), "l"(src));
}
__device__ __forceinline__ void cp_commit() {
    asm volatile("cp.async.commit_group;");
}
__device__ __forceinline__ void cp_wait0() {
    asm volatile("cp.async.wait_group 0;" ::: "memory");
}
// m16n8k16 row.col fp16 -> f32 accum (base PTX)
__device__ __forceinline__ void mma_f16(float c[4], const uint32_t a[4],
                                        uint32_t b0, uint32_t b1) {
    asm volatile(
        "mma.sync.aligned.m16n8k16.row.col.f32.f16.f16.f32 "
        "{%0,%1,%2,%3}, {%4,%5,%6,%7}, {%8,%9}, {%0,%1,%2,%3};"
        : "+f"(c[0]), "+f"(c[1]), "+f"(c[2]), "+f"(c[3])
        : "r"(a[0]), "r"(a[1]), "r"(a[2]), "r"(a[3]), "r"(b0), "r"(b1));
}
__device__ __forceinline__ void ldm_x4(uint32_t* r, uint32_t a) {
    asm volatile("ldmatrix.sync.aligned.m8n8.x4.shared.b16 {%0,%1,%2,%3}, [%4];"
                 : "=r"(r[0]), "=r"(r[1]), "=r"(r[2]), "=r"(r[3]) : "r"(a));
}
__device__ __forceinline__ int expert_of(int row0) {
    int e = 0;
#pragma unroll
    for (int i = 1; i < NEXP; i++) if (row0 >= g_offsets[i]) e = i;
    return e;
}

// ---------------- launch 0: gating (1 warp / token) ------
__global__ void gating_kernel(const float* __restrict__ x, const float* __restrict__ gw) {
    int t = (blockIdx.x * blockDim.x + threadIdx.x) >> 5;
    int lane = threadIdx.x & 31;
    if (t >= T_TOK) return;
    const float* xr = x + (size_t)t * DIM;
    float xv[DIM / 32];
#pragma unroll
    for (int i = 0; i < DIM / 32; i++) xv[i] = xr[lane + 32 * i];
    float logits[NEXP];
#pragma unroll
    for (int e = 0; e < NEXP; e++) {
        const float* g = gw + e * DIM;
        float acc = 0.f;
#pragma unroll
        for (int i = 0; i < DIM / 32; i++) acc = fmaf(xv[i], g[lane + 32 * i], acc);
#pragma unroll
        for (int o = 16; o; o >>= 1) acc += __shfl_xor_sync(0xffffffffu, acc, o);
        logits[e] = acc;
    }
    if (lane == 0) {
        int e0 = 0; float l0 = logits[0];
#pragma unroll
        for (int e = 1; e < NEXP; e++) if (logits[e] > l0) { l0 = logits[e]; e0 = e; }
        int e1 = (e0 == 0) ? 1 : 0; float l1 = logits[e1];
#pragma unroll
        for (int e = 0; e < NEXP; e++) if (e != e0 && logits[e] > l1) { l1 = logits[e]; e1 = e; }
        float p1 = __expf(l1 - l0);
        float inv = 1.f / (1.f + p1);
        g_sel[t * 2 + 0] = e0; g_sel[t * 2 + 1] = e1;
        g_gwt[t * 2 + 0] = inv; g_gwt[t * 2 + 1] = p1 * inv;
    }
}

// ---------------- launch 1: count + scan + scatter (single block) -----------
__global__ __launch_bounds__(1024) void scatscan_kernel() {
    __shared__ int scnt[NEXP];
    __shared__ int scur[NEXP];
    int tid = threadIdx.x;
    if (tid < NEXP) scnt[tid] = 0;
    __syncthreads();
    for (int idx = tid; idx < NSLOT; idx += 1024)
        atomicAdd(&scnt[g_sel[idx]], 1);
    __syncthreads();
    if (tid == 0) {
        int o = 0;
        for (int e = 0; e < NEXP; e++) {
            int c = scnt[e];
            int cp = (c + 127) & ~127;
            g_counts[e] = c;
            g_offsets[e] = o;
            g_cntpad[e] = cp;
            scur[e] = o;
            o += cp;
        }
    }
    __syncthreads();
    for (int idx = tid; idx < NSLOT; idx += 1024) {
        int e = g_sel[idx];
        int pos = atomicAdd(&scur[e], 1);
        g_perm[pos] = idx >> 1;
        g_rowOf[idx] = pos;
    }
}

// ---------------- launch 2: prep = gather(x->fp16) + weight convert ---------
#define WQ ((size_t)NEXP*HID*DIM/4)
#define WBLK ((unsigned)((3*WQ + 255) / 256))
__global__ __launch_bounds__(256) void prep_kernel(const float* __restrict__ x,
                                                   const float* __restrict__ w1,
                                                   const float* __restrict__ w3,
                                                   const float* __restrict__ w2) {
    int b = blockIdx.x;
    if (b < PADT) {
        int row = b;
        int e = -1, r = 0;
#pragma unroll
        for (int i = 0; i < NEXP; i++) {
            int o = g_offsets[i], c = g_cntpad[i];
            if (row >= o && row < o + c) { e = i; r = row - o; }
        }
        if (e < 0) return;
        float4 v = make_float4(0.f, 0.f, 0.f, 0.f);
        if (r < g_counts[e]) {
            int tok = g_perm[row];
            v = *(const float4*)(x + (size_t)tok * DIM + threadIdx.x * 4);
        }
        size_t o = (size_t)row * DIM + threadIdx.x * 4;
        __half2 a0, a1;
        a0.x = __float2half_rn(v.x); a0.y = __float2half_rn(v.y);
        a1.x = __float2half_rn(v.z); a1.y = __float2half_rn(v.w);
        ((__half2*)(g_x + o))[0] = a0;
        ((__half2*)(g_x + o))[1] = a1;
    } else {
        size_t i = (size_t)(b - PADT) * 256 + threadIdx.x;
        if (i >= 3 * WQ) return;
        const float* src; __half* hi; size_t j;
        if (i < WQ)          { src = w1; hi = g_w1h; j = i; }
        else if (i < 2 * WQ) { src = w3; hi = g_w3h; j = i - WQ; }
        else                 { src = w2; hi = g_w2h; j = i - 2 * WQ; }
        float4 v = ((const float4*)src)[j];
        __half2 h0, h1;
        h0.x = __float2half_rn(v.x); h0.y = __float2half_rn(v.y);
        h1.x = __float2half_rn(v.z); h1.y = __float2half_rn(v.w);
        ((__half2*)(hi + 4 * j))[0] = h0;
        ((__half2*)(hi + 4 * j))[1] = h1;
    }
}

// ---------------- shared memory layouts ----------------
// GEMM1: K-chunk 64 (128B rows + 16B pad), 1-pass
#define SAW 144
#define G1_A   0
#define G1_B1H 18432
#define G1_B3H 27648
#define G1_STAGE 36864
#define G1_SMEM (2*G1_STAGE)    // 73728/CTA, 2 CTAs = 144 KB
// GEMM2: K-chunk 128 (256B rows + 16B pad), 1-pass
#define SAW2 272
#define G2_A   0
#define G2_BH  34816            // 128*272
#define G2_STAGE 52224          // + 64*272
#define G2_SMEM (2*G2_STAGE)    // 104448/CTA, 2 CTAs = 204 KB

// ---------------- GEMM1: hidden = silu(x@w1^T) * (x@w3^T), fp16 1-pass ------
__device__ __forceinline__ void g1_load(uint32_t st,
        const __half* A, const __half* B1h, const __half* B3h, int kt, int tid) {
#pragma unroll
    for (int i = 0; i < 4; i++) {
        int idx = tid + i * 256;
        int m = idx >> 3, c = idx & 7;
        cp16(st + G1_A + m * SAW + c * 16, A + (size_t)m * DIM + kt + c * 8);
    }
#pragma unroll
    for (int i = 0; i < 2; i++) {
        int idx = tid + i * 256;
        int n = idx >> 3, c = idx & 7;
        cp16(st + G1_B1H + n * SAW + c * 16, B1h + (size_t)n * DIM + kt + c * 8);
        cp16(st + G1_B3H + n * SAW + c * 16, B3h + (size_t)n * DIM + kt + c * 8);
    }
}

__global__ __launch_bounds__(256, 2) void gemm1_mma() {
    int row0 = blockIdx.y * 128;
    if (row0 >= g_offsets[NEXP - 1] + g_cntpad[NEXP - 1]) return;
    int e = expert_of(row0);
    int n0 = blockIdx.x * 64;

    extern __shared__ __align__(16) char smem[];
    uint32_t sb = smem_u32(smem);
    int tid = threadIdx.x, lane = tid & 31, warp = tid >> 5;
    int gr = lane >> 2, gc2 = (lane & 3) * 2;
    int wm = (warp & 3) * 32;
    int wn = (warp >> 2) * 32;

    const __half* A   = g_x + (size_t)row0 * DIM;
    const size_t wb = ((size_t)e * HID + n0) * DIM;
    const __half* B1h = g_w1h + wb;
    const __half* B3h = g_w3h + wb;

    float acc1[2][4][4], acc3[2][4][4];
#pragma unroll
    for (int i = 0; i < 2; i++)
#pragma unroll
        for (int j = 0; j < 4; j++)
#pragma unroll
            for (int q = 0; q < 4; q++) { acc1[i][j][q] = 0.f; acc3[i][j][q] = 0.f; }

    uint32_t aAddr = (lane & 15) * SAW + (lane >> 4) * 16;
    uint32_t bAddr = (((lane >> 4) & 1) * 8 + (lane & 7)) * SAW + ((lane >> 3) & 1) * 16;

    const int NK = DIM / 64;   // 16
    g1_load(sb, A, B1h, B3h, 0, tid);
    cp_commit();

#pragma unroll 1
    for (int kc = 0; kc < NK; kc++) {
        cp_wait0();
        __syncthreads();
        if (kc + 1 < NK) {
            g1_load(sb + ((kc + 1) & 1) * G1_STAGE, A, B1h, B3h, (kc + 1) * 64, tid);
            cp_commit();
        }
        uint32_t stv = sb + (kc & 1) * G1_STAGE;
#pragma unroll
        for (int ks = 0; ks < 4; ks++) {
            uint32_t k0b = ks * 32;
            uint32_t a[2][4];
#pragma unroll
            for (int i = 0; i < 2; i++)
                ldm_x4(a[i], stv + G1_A + (wm + i * 16) * SAW + aAddr + k0b);
#pragma unroll
            for (int jp = 0; jp < 2; jp++) {
                uint32_t rb = (wn + jp * 16) * SAW + bAddr + k0b;
                int j0 = jp * 2, j1 = jp * 2 + 1;
                uint32_t b1[4], b3[4];
                ldm_x4(b1, stv + G1_B1H + rb);
                ldm_x4(b3, stv + G1_B3H + rb);
#pragma unroll
                for (int i = 0; i < 2; i++) {
                    mma_f16(acc1[i][j0], a[i], b1[0], b1[1]);
                    mma_f16(acc1[i][j1], a[i], b1[2], b1[3]);
                    mma_f16(acc3[i][j0], a[i], b3[0], b3[1]);
                    mma_f16(acc3[i][j1], a[i], b3[2], b3[3]);
                }
            }
        }
    }

    // epilogue: silu(h1)*h3 -> fp16 hidden
#pragma unroll
    for (int i = 0; i < 2; i++)
#pragma unroll
        for (int j = 0; j < 4; j++) {
            int m = wm + i * 16 + gr;
            int n = wn + j * 8 + gc2;
#pragma unroll
            for (int half = 0; half < 2; half++) {
                int mm = m + half * 8;
                float h1a = acc1[i][j][half * 2 + 0], h1b = acc1[i][j][half * 2 + 1];
                float h3a = acc3[i][j][half * 2 + 0], h3b = acc3[i][j][half * 2 + 1];
                float v0 = h3a * h1a / (1.f + __expf(-h1a));
                float v1 = h3b * h1b / (1.f + __expf(-h1b));
                __half2 hv;
                hv.x = __float2half_rn(v0);
                hv.y = __float2half_rn(v1);
                *(__half2*)(g_h + (size_t)(row0 + mm) * HID + n0 + n) = hv;
            }
        }
}

// ---------------- GEMM2: y = hidden @ w2h^T, fp16 1-pass, K-chunk 128 -------
__device__ __forceinline__ void g2_load(uint32_t st,
        const __half* A, const __half* Bh, int kt, int tid) {
#pragma unroll
    for (int i = 0; i < 8; i++) {
        int idx = tid + i * 256;
        int m = idx >> 4, c = idx & 15;
        cp16(st + G2_A + m * SAW2 + c * 16, A + (size_t)m * HID + kt + c * 8);
    }
#pragma unroll
    for (int i = 0; i < 4; i++) {
        int idx = tid + i * 256;
        int n = idx >> 4, c = idx & 15;
        cp16(st + G2_BH + n * SAW2 + c * 16, Bh + (size_t)n * HID + kt + c * 8);
    }
}

__global__ __launch_bounds__(256, 2) void gemm2_mma() {
    int row0 = blockIdx.y * 128;
    if (row0 >= g_offsets[NEXP - 1] + g_cntpad[NEXP - 1]) return;
    int e = expert_of(row0);
    int n0 = blockIdx.x * 64;

    extern __shared__ __align__(16) char smem[];
    uint32_t sb = smem_u32(smem);
    int tid = threadIdx.x, lane = tid & 31, warp = tid >> 5;
    int gr = lane >> 2, gc2 = (lane & 3) * 2;
    int wm = (warp & 3) * 32;
    int wn = (warp >> 2) * 32;

    const __half* A  = g_h + (size_t)row0 * HID;
    const __half* Bh = g_w2h + ((size_t)e * DIM + n0) * HID;

    float acc[2][4][4];
#pragma unroll
    for (int i = 0; i < 2; i++)
#pragma unroll
        for (int j = 0; j < 4; j++)
#pragma unroll
            for (int q = 0; q < 4; q++) acc[i][j][q] = 0.f;

    uint32_t aAddr = (lane & 15) * SAW2 + (lane >> 4) * 16;
    uint32_t bAddr = (((lane >> 4) & 1) * 8 + (lane & 7)) * SAW2 + ((lane >> 3) & 1) * 16;

    const int NK = HID / 128;   // 16
    g2_load(sb, A, Bh, 0, tid);
    cp_commit();

#pragma unroll 1
    for (int kc = 0; kc < NK; kc++) {
        cp_wait0();
        __syncthreads();
        if (kc + 1 < NK) {
            g2_load(sb + ((kc + 1) & 1) * G2_STAGE, A, Bh, (kc + 1) * 128, tid);
            cp_commit();
        }
        uint32_t stv = sb + (kc & 1) * G2_STAGE;
#pragma unroll
        for (int ks = 0; ks < 8; ks++) {
            uint32_t k0b = ks * 32;
            uint32_t a[2][4];
#pragma unroll
            for (int i = 0; i < 2; i++)
                ldm_x4(a[i], stv + G2_A + (wm + i * 16) * SAW2 + aAddr + k0b);
#pragma unroll
            for (int jp = 0; jp < 2; jp++) {
                uint32_t rb = (wn + jp * 16) * SAW2 + bAddr + k0b;
                int j0 = jp * 2, j1 = jp * 2 + 1;
                uint32_t bh[4];
                ldm_x4(bh, stv + G2_BH + rb);
#pragma unroll
                for (int i = 0; i < 2; i++) {
                    mma_f16(acc[i][j0], a[i], bh[0], bh[1]);
                    mma_f16(acc[i][j1], a[i], bh[2], bh[3]);
                }
            }
        }
    }

#pragma unroll
    for (int i = 0; i < 2; i++)
#pragma unroll
        for (int j = 0; j < 4; j++) {
            int m = wm + i * 16 + gr;
            int n = wn + j * 8 + gc2;
#pragma unroll
            for (int half = 0; half < 2; half++) {
                int mm = m + half * 8;
                float2 v = make_float2(acc[i][j][half * 2 + 0], acc[i][j][half * 2 + 1]);
                *(float2*)(g_y + (size_t)(row0 + mm) * DIM + n0 + n) = v;
            }
        }
}

// ---------------- launch 5: combine ----------------
__global__ void combine_kernel(float* __restrict__ out) {
    int idx = blockIdx.x * blockDim.x + threadIdx.x;
    if (idx >= T_TOK * DIM / 4) return;
    int t = idx / (DIM / 4);
    int d4 = idx - t * (DIM / 4);
    float w0 = g_gwt[t * 2 + 0], w1 = g_gwt[t * 2 + 1];
    const float4 y0 = *(const float4*)(g_y + (size_t)g_rowOf[t * 2 + 0] * DIM + d4 * 4);
    const float4 y1 = *(const float4*)(g_y + (size_t)g_rowOf[t * 2 + 1] * DIM + d4 * 4);
    float4 o;
    o.x = w0 * y0.x + w1 * y1.x;
    o.y = w0 * y0.y + w1 * y1.y;
    o.z = w0 * y0.z + w1 * y1.z;
    o.w = w0 * y0.w + w1 * y1.w;
    ((float4*)out)[idx] = o;
}

// ---------------- launch ----------------
extern "C" void kernel_launch(void* const* d_in, const int* in_sizes, int n_in,
                              void* d_out, int out_size) {
    const float* x  = (const float*)d_in[0];
    const float* gw = (const float*)d_in[1];
    const float* w1 = (const float*)d_in[2];
    const float* w3 = (const float*)d_in[3];
    const float* w2 = (const float*)d_in[4];
    float* out = (float*)d_out;

    cudaFuncSetAttribute(gemm1_mma, cudaFuncAttributeMaxDynamicSharedMemorySize, G1_SMEM);
    cudaFuncSetAttribute(gemm2_mma, cudaFuncAttributeMaxDynamicSharedMemorySize, G2_SMEM);

    gating_kernel<<<T_TOK / 8, 256>>>(x, gw);                          // 0
    scatscan_kernel<<<1, 1024>>>();                                    // 1
    prep_kernel<<<PADT + WBLK, 256>>>(x, w1, w3, w2);                  // 2
    gemm1_mma<<<dim3(HID / 64, ROWB), 256, G1_SMEM>>>();               // 3 (ncu -s 5 target)
    gemm2_mma<<<dim3(DIM / 64, ROWB), 256, G2_SMEM>>>();               // 4
    combine_kernel<<<(T_TOK * DIM / 4 + 255) / 256, 256>>>(out);       // 5
}

// round 16
// speedup vs baseline: 2.9969x; 1.0776x over previous
#include <cuda_runtime.h>
#include <cuda_fp16.h>
#include <math.h>
#include <stdint.h>

// ---------------- problem constants ----------------
#define T_TOK 16384
#define DIM   1024
#define HID   2048
#define NEXP  8
#define TOPK  2
#define NSLOT (T_TOK*TOPK)                 // 32768
#define PADT  (NSLOT + NEXP*128)           // 33792 padded rows
#define ROWB  (PADT/128)                   // 264 row-blocks

// ---------------- device scratch (allocation-free rule) ----------------
__device__ int   g_counts[NEXP];
__device__ int   g_cntpad[NEXP];
__device__ int   g_offsets[NEXP];
__device__ int   g_perm[PADT];
__device__ int   g_rowOf[NSLOT];
__device__ int   g_sel[NSLOT];
__device__ float g_gwt[NSLOT];

// fp16 weights (1-pass); fp16 activations, hidden and y
__device__ __half g_w1h[(size_t)NEXP*HID*DIM];
__device__ __half g_w3h[(size_t)NEXP*HID*DIM];
__device__ __half g_w2h[(size_t)NEXP*DIM*HID];
__device__ __half g_x [(size_t)PADT*DIM];
__device__ __half g_h [(size_t)PADT*HID];
__device__ __half g_y [(size_t)PADT*DIM];

// ---------------- helpers (base-PTX only) ----------------
__device__ __forceinline__ uint32_t smem_u32(const void* p) {
    uint32_t a;
    asm("{ .reg .u64 t; cvta.to.shared.u64 t, %1; cvt.u32.u64 %0, t; }" : "=r"(a) : "l"(p));
    return a;
}
__device__ __forceinline__ void cp16(uint32_t dst, const void* src) {
    asm volatile("cp.async.cg.shared.global [%0], [%1], 16;" :: "r"(dst), "l"(src));
}
__device__ __forceinline__ void cp_commit() {
    asm volatile("cp.async.commit_group;");
}
__device__ __forceinline__ void cp_wait0() {
    asm volatile("cp.async.wait_group 0;" ::: "memory");
}
// m16n8k16 row.col fp16 -> f32 accum (base PTX)
__device__ __forceinline__ void mma_f16(float c[4], const uint32_t a[4],
                                        uint32_t b0, uint32_t b1) {
    asm volatile(
        "mma.sync.aligned.m16n8k16.row.col.f32.f16.f16.f32 "
        "{%0,%1,%2,%3}, {%4,%5,%6,%7}, {%8,%9}, {%0,%1,%2,%3};"
        : "+f"(c[0]), "+f"(c[1]), "+f"(c[2]), "+f"(c[3])
        : "r"(a[0]), "r"(a[1]), "r"(a[2]), "r"(a[3]), "r"(b0), "r"(b1));
}
__device__ __forceinline__ void ldm_x4(uint32_t* r, uint32_t a) {
    asm volatile("ldmatrix.sync.aligned.m8n8.x4.shared.b16 {%0,%1,%2,%3}, [%4];"
                 : "=r"(r[0]), "=r"(r[1]), "=r"(r[2]), "=r"(r[3]) : "r"(a));
}
__device__ __forceinline__ int expert_of(int row0) {
    int e = 0;
#pragma unroll
    for (int i = 1; i < NEXP; i++) if (row0 >= g_offsets[i]) e = i;
    return e;
}

// ---------------- launch 0: gating (1 warp / token) ------
__global__ void gating_kernel(const float* __restrict__ x, const float* __restrict__ gw) {
    int t = (blockIdx.x * blockDim.x + threadIdx.x) >> 5;
    int lane = threadIdx.x & 31;
    if (t >= T_TOK) return;
    const float* xr = x + (size_t)t * DIM;
    float xv[DIM / 32];
#pragma unroll
    for (int i = 0; i < DIM / 32; i++) xv[i] = xr[lane + 32 * i];
    float logits[NEXP];
#pragma unroll
    for (int e = 0; e < NEXP; e++) {
        const float* g = gw + e * DIM;
        float acc = 0.f;
#pragma unroll
        for (int i = 0; i < DIM / 32; i++) acc = fmaf(xv[i], g[lane + 32 * i], acc);
#pragma unroll
        for (int o = 16; o; o >>= 1) acc += __shfl_xor_sync(0xffffffffu, acc, o);
        logits[e] = acc;
    }
    if (lane == 0) {
        int e0 = 0; float l0 = logits[0];
#pragma unroll
        for (int e = 1; e < NEXP; e++) if (logits[e] > l0) { l0 = logits[e]; e0 = e; }
        int e1 = (e0 == 0) ? 1 : 0; float l1 = logits[e1];
#pragma unroll
        for (int e = 0; e < NEXP; e++) if (e != e0 && logits[e] > l1) { l1 = logits[e]; e1 = e; }
        float p1 = __expf(l1 - l0);
        float inv = 1.f / (1.f + p1);
        g_sel[t * 2 + 0] = e0; g_sel[t * 2 + 1] = e1;
        g_gwt[t * 2 + 0] = inv; g_gwt[t * 2 + 1] = p1 * inv;
    }
}

// ---------------- launch 1: count + scan + scatter (single block) -----------
__global__ __launch_bounds__(1024) void scatscan_kernel() {
    __shared__ int scnt[NEXP];
    __shared__ int scur[NEXP];
    int tid = threadIdx.x;
    if (tid < NEXP) scnt[tid] = 0;
    __syncthreads();
    for (int idx = tid; idx < NSLOT; idx += 1024)
        atomicAdd(&scnt[g_sel[idx]], 1);
    __syncthreads();
    if (tid == 0) {
        int o = 0;
        for (int e = 0; e < NEXP; e++) {
            int c = scnt[e];
            int cp = (c + 127) & ~127;
            g_counts[e] = c;
            g_offsets[e] = o;
            g_cntpad[e] = cp;
            scur[e] = o;
            o += cp;
        }
    }
    __syncthreads();
    for (int idx = tid; idx < NSLOT; idx += 1024) {
        int e = g_sel[idx];
        int pos = atomicAdd(&scur[e], 1);
        g_perm[pos] = idx >> 1;
        g_rowOf[idx] = pos;
    }
}

// ---------------- launch 2: prep = gather(x->fp16) + weight convert ---------
#define WQ ((size_t)NEXP*HID*DIM/4)
#define WBLK ((unsigned)((3*WQ + 255) / 256))
__global__ __launch_bounds__(256) void prep_kernel(const float* __restrict__ x,
                                                   const float* __restrict__ w1,
                                                   const float* __restrict__ w3,
                                                   const float* __restrict__ w2) {
    int b = blockIdx.x;
    if (b < PADT) {
        int row = b;
        int e = -1, r = 0;
#pragma unroll
        for (int i = 0; i < NEXP; i++) {
            int o = g_offsets[i], c = g_cntpad[i];
            if (row >= o && row < o + c) { e = i; r = row - o; }
        }
        if (e < 0) return;
        float4 v = make_float4(0.f, 0.f, 0.f, 0.f);
        if (r < g_counts[e]) {
            int tok = g_perm[row];
            v = *(const float4*)(x + (size_t)tok * DIM + threadIdx.x * 4);
        }
        size_t o = (size_t)row * DIM + threadIdx.x * 4;
        __half2 a0, a1;
        a0.x = __float2half_rn(v.x); a0.y = __float2half_rn(v.y);
        a1.x = __float2half_rn(v.z); a1.y = __float2half_rn(v.w);
        ((__half2*)(g_x + o))[0] = a0;
        ((__half2*)(g_x + o))[1] = a1;
    } else {
        size_t i = (size_t)(b - PADT) * 256 + threadIdx.x;
        if (i >= 3 * WQ) return;
        const float* src; __half* hi; size_t j;
        if (i < WQ)          { src = w1; hi = g_w1h; j = i; }
        else if (i < 2 * WQ) { src = w3; hi = g_w3h; j = i - WQ; }
        else                 { src = w2; hi = g_w2h; j = i - 2 * WQ; }
        float4 v = ((const float4*)src)[j];
        __half2 h0, h1;
        h0.x = __float2half_rn(v.x); h0.y = __float2half_rn(v.y);
        h1.x = __float2half_rn(v.z); h1.y = __float2half_rn(v.w);
        ((__half2*)(hi + 4 * j))[0] = h0;
        ((__half2*)(hi + 4 * j))[1] = h1;
    }
}

// ---------------- shared memory layouts (K-chunk 64, 128B rows + 16B pad) ---
#define SAW 144
// GEMM1: A [128x64], B1/B3 [64x64]
#define G1_A   0
#define G1_B1H 18432
#define G1_B3H 27648
#define G1_STAGE 36864
#define G1_SMEM (2*G1_STAGE)    // 73728/CTA, 2 CTAs = 144 KB
// GEMM2: A [128x64], B [128x64] (CTA tile 128x128)
#define G2_A   0
#define G2_BH  18432
#define G2_STAGE 36864
#define G2_SMEM (2*G2_STAGE)    // 73728/CTA, 2 CTAs = 144 KB

// ---------------- GEMM1: hidden = silu(x@w1^T) * (x@w3^T), fp16 1-pass ------
__device__ __forceinline__ void g1_load(uint32_t st,
        const __half* A, const __half* B1h, const __half* B3h, int kt, int tid) {
#pragma unroll
    for (int i = 0; i < 4; i++) {
        int idx = tid + i * 256;
        int m = idx >> 3, c = idx & 7;
        cp16(st + G1_A + m * SAW + c * 16, A + (size_t)m * DIM + kt + c * 8);
    }
#pragma unroll
    for (int i = 0; i < 2; i++) {
        int idx = tid + i * 256;
        int n = idx >> 3, c = idx & 7;
        cp16(st + G1_B1H + n * SAW + c * 16, B1h + (size_t)n * DIM + kt + c * 8);
        cp16(st + G1_B3H + n * SAW + c * 16, B3h + (size_t)n * DIM + kt + c * 8);
    }
}

__global__ __launch_bounds__(256, 2) void gemm1_mma() {
    int row0 = blockIdx.y * 128;
    if (row0 >= g_offsets[NEXP - 1] + g_cntpad[NEXP - 1]) return;
    int e = expert_of(row0);
    int n0 = blockIdx.x * 64;

    extern __shared__ __align__(16) char smem[];
    uint32_t sb = smem_u32(smem);
    int tid = threadIdx.x, lane = tid & 31, warp = tid >> 5;
    int gr = lane >> 2, gc2 = (lane & 3) * 2;
    int wm = (warp & 3) * 32;
    int wn = (warp >> 2) * 32;

    const __half* A   = g_x + (size_t)row0 * DIM;
    const size_t wb = ((size_t)e * HID + n0) * DIM;
    const __half* B1h = g_w1h + wb;
    const __half* B3h = g_w3h + wb;

    float acc1[2][4][4], acc3[2][4][4];
#pragma unroll
    for (int i = 0; i < 2; i++)
#pragma unroll
        for (int j = 0; j < 4; j++)
#pragma unroll
            for (int q = 0; q < 4; q++) { acc1[i][j][q] = 0.f; acc3[i][j][q] = 0.f; }

    uint32_t aAddr = (lane & 15) * SAW + (lane >> 4) * 16;
    uint32_t bAddr = (((lane >> 4) & 1) * 8 + (lane & 7)) * SAW + ((lane >> 3) & 1) * 16;

    const int NK = DIM / 64;   // 16
    g1_load(sb, A, B1h, B3h, 0, tid);
    cp_commit();

#pragma unroll 1
    for (int kc = 0; kc < NK; kc++) {
        cp_wait0();
        __syncthreads();
        if (kc + 1 < NK) {
            g1_load(sb + ((kc + 1) & 1) * G1_STAGE, A, B1h, B3h, (kc + 1) * 64, tid);
            cp_commit();
        }
        uint32_t stv = sb + (kc & 1) * G1_STAGE;
#pragma unroll
        for (int ks = 0; ks < 4; ks++) {
            uint32_t k0b = ks * 32;
            uint32_t a[2][4];
#pragma unroll
            for (int i = 0; i < 2; i++)
                ldm_x4(a[i], stv + G1_A + (wm + i * 16) * SAW + aAddr + k0b);
#pragma unroll
            for (int jp = 0; jp < 2; jp++) {
                uint32_t rb = (wn + jp * 16) * SAW + bAddr + k0b;
                int j0 = jp * 2, j1 = jp * 2 + 1;
                uint32_t b1[4], b3[4];
                ldm_x4(b1, stv + G1_B1H + rb);
                ldm_x4(b3, stv + G1_B3H + rb);
#pragma unroll
                for (int i = 0; i < 2; i++) {
                    mma_f16(acc1[i][j0], a[i], b1[0], b1[1]);
                    mma_f16(acc1[i][j1], a[i], b1[2], b1[3]);
                    mma_f16(acc3[i][j0], a[i], b3[0], b3[1]);
                    mma_f16(acc3[i][j1], a[i], b3[2], b3[3]);
                }
            }
        }
    }

    // epilogue: silu(h1)*h3 -> fp16 hidden
#pragma unroll
    for (int i = 0; i < 2; i++)
#pragma unroll
        for (int j = 0; j < 4; j++) {
            int m = wm + i * 16 + gr;
            int n = wn + j * 8 + gc2;
#pragma unroll
            for (int half = 0; half < 2; half++) {
                int mm = m + half * 8;
                float h1a = acc1[i][j][half * 2 + 0], h1b = acc1[i][j][half * 2 + 1];
                float h3a = acc3[i][j][half * 2 + 0], h3b = acc3[i][j][half * 2 + 1];
                float v0 = h3a * h1a / (1.f + __expf(-h1a));
                float v1 = h3b * h1b / (1.f + __expf(-h1b));
                __half2 hv;
                hv.x = __float2half_rn(v0);
                hv.y = __float2half_rn(v1);
                *(__half2*)(g_h + (size_t)(row0 + mm) * HID + n0 + n) = hv;
            }
        }
}

// ---------------- GEMM2: y = hidden @ w2h^T, CTA 128x128, K-chunk 64 --------
__device__ __forceinline__ void g2_load(uint32_t st,
        const __half* A, const __half* Bh, int kt, int tid) {
#pragma unroll
    for (int i = 0; i < 4; i++) {
        int idx = tid + i * 256;
        int m = idx >> 3, c = idx & 7;
        cp16(st + G2_A + m * SAW + c * 16, A + (size_t)m * HID + kt + c * 8);
        cp16(st + G2_BH + m * SAW + c * 16, Bh + (size_t)m * HID + kt + c * 8);
    }
}

__global__ __launch_bounds__(256, 2) void gemm2_mma() {
    int row0 = blockIdx.y * 128;
    if (row0 >= g_offsets[NEXP - 1] + g_cntpad[NEXP - 1]) return;
    int e = expert_of(row0);
    int n0 = blockIdx.x * 128;

    extern __shared__ __align__(16) char smem[];
    uint32_t sb = smem_u32(smem);
    int tid = threadIdx.x, lane = tid & 31, warp = tid >> 5;
    int gr = lane >> 2, gc2 = (lane & 3) * 2;
    int wm = (warp & 3) * 32;      // 4 warps along M
    int wn = (warp >> 2) * 64;     // 2 warps along N (64 each)

    const __half* A  = g_h + (size_t)row0 * HID;
    const __half* Bh = g_w2h + ((size_t)e * DIM + n0) * HID;

    float acc[2][8][4];
#pragma unroll
    for (int i = 0; i < 2; i++)
#pragma unroll
        for (int j = 0; j < 8; j++)
#pragma unroll
            for (int q = 0; q < 4; q++) acc[i][j][q] = 0.f;

    uint32_t aAddr = (lane & 15) * SAW + (lane >> 4) * 16;
    uint32_t bAddr = (((lane >> 4) & 1) * 8 + (lane & 7)) * SAW + ((lane >> 3) & 1) * 16;

    const int NK = HID / 64;   // 32
    g2_load(sb, A, Bh, 0, tid);
    cp_commit();

#pragma unroll 1
    for (int kc = 0; kc < NK; kc++) {
        cp_wait0();
        __syncthreads();
        if (kc + 1 < NK) {
            g2_load(sb + ((kc + 1) & 1) * G2_STAGE, A, Bh, (kc + 1) * 64, tid);
            cp_commit();
        }
        uint32_t stv = sb + (kc & 1) * G2_STAGE;
#pragma unroll
        for (int ks = 0; ks < 4; ks++) {
            uint32_t k0b = ks * 32;
            uint32_t a[2][4];
#pragma unroll
            for (int i = 0; i < 2; i++)
                ldm_x4(a[i], stv + G2_A + (wm + i * 16) * SAW + aAddr + k0b);
#pragma unroll
            for (int jp = 0; jp < 4; jp++) {
                uint32_t rb = (wn + jp * 16) * SAW + bAddr + k0b;
                int j0 = jp * 2, j1 = jp * 2 + 1;
                uint32_t bh[4];
                ldm_x4(bh, stv + G2_BH + rb);
#pragma unroll
                for (int i = 0; i < 2; i++) {
                    mma_f16(acc[i][j0], a[i], bh[0], bh[1]);
                    mma_f16(acc[i][j1], a[i], bh[2], bh[3]);
                }
            }
        }
    }

    // epilogue -> fp16 y
#pragma unroll
    for (int i = 0; i < 2; i++)
#pragma unroll
        for (int j = 0; j < 8; j++) {
            int m = wm + i * 16 + gr;
            int n = wn + j * 8 + gc2;
#pragma unroll
            for (int half = 0; half < 2; half++) {
                int mm = m + half * 8;
                __half2 hv;
                hv.x = __float2half_rn(acc[i][j][half * 2 + 0]);
                hv.y = __float2half_rn(acc[i][j][half * 2 + 1]);
                *(__half2*)(g_y + (size_t)(row0 + mm) * DIM + n0 + n) = hv;
            }
        }
}

// ---------------- launch 5: combine (fp16 y -> fp32 out) --------------------
__global__ void combine_kernel(float* __restrict__ out) {
    int idx = blockIdx.x * blockDim.x + threadIdx.x;
    if (idx >= T_TOK * DIM / 4) return;
    int t = idx / (DIM / 4);
    int d4 = idx - t * (DIM / 4);
    float w0 = g_gwt[t * 2 + 0], w1 = g_gwt[t * 2 + 1];
    const __half2* y0 = (const __half2*)(g_y + (size_t)g_rowOf[t * 2 + 0] * DIM + d4 * 4);
    const __half2* y1 = (const __half2*)(g_y + (size_t)g_rowOf[t * 2 + 1] * DIM + d4 * 4);
    __half2 a0 = y0[0], a1 = y0[1];
    __half2 b0 = y1[0], b1 = y1[1];
    float4 o;
    o.x = w0 * __half2float(a0.x) + w1 * __half2float(b0.x);
    o.y = w0 * __half2float(a0.y) + w1 * __half2float(b0.y);
    o.z = w0 * __half2float(a1.x) + w1 * __half2float(b1.x);
    o.w = w0 * __half2float(a1.y) + w1 * __half2float(b1.y);
    ((float4*)out)[idx] = o;
}

// ---------------- launch ----------------
extern "C" void kernel_launch(void* const* d_in, const int* in_sizes, int n_in,
                              void* d_out, int out_size) {
    const float* x  = (const float*)d_in[0];
    const float* gw = (const float*)d_in[1];
    const float* w1 = (const float*)d_in[2];
    const float* w3 = (const float*)d_in[3];
    const float* w2 = (const float*)d_in[4];
    float* out = (float*)d_out;

    cudaFuncSetAttribute(gemm1_mma, cudaFuncAttributeMaxDynamicSharedMemorySize, G1_SMEM);
    cudaFuncSetAttribute(gemm2_mma, cudaFuncAttributeMaxDynamicSharedMemorySize, G2_SMEM);

    gating_kernel<<<T_TOK / 8, 256>>>(x, gw);                          // 0
    scatscan_kernel<<<1, 1024>>>();                                    // 1
    prep_kernel<<<PADT + WBLK, 256>>>(x, w1, w3, w2);                  // 2
    gemm1_mma<<<dim3(HID / 64, ROWB), 256, G1_SMEM>>>();               // 3 (ncu -s 5 target)
    gemm2_mma<<<dim3(DIM / 128, ROWB), 256, G2_SMEM>>>();              // 4
    combine_kernel<<<(T_TOK * DIM / 4 + 255) / 256, 256>>>(out);       // 5
}